// round 10
// baseline (speedup 1.0000x reference)
#include <cuda_runtime.h>
#include <cuda_fp16.h>
#include <math.h>
#include <stdint.h>

#define N_NODES 8192
#define D_DIM   512
#define H_HEADS 8
#define DKV     64
#define DEG     16
#define E_EDGES (N_NODES*DEG)          // 131072
#define FEAT_COLS 544

// split-fp16 2-term GEMM geometry
#define K1 1024            // proj: 2*512
#define B1_ROWS 1664       // 512(q)+512(k)+512(v)+24(qv) = 1560, padded to 13*128
#define C1_LD 1664
#define K2 1088            // out: 2*544 (exact, no padding)
#define QV_OFF 1536
#define STAGES 3
#define BK 64
#define STAGE_BYTES (128 * BK * 2)     // 16384 per operand per stage

// ---------------- device-global scratch (no allocations allowed) ------------
__device__ __half g_A1[(size_t)N_NODES * K1];     // [x_hi | x_lo]
__device__ __half g_B1[(size_t)B1_ROWS * K1];     // [W_hi | W_hi], pad rows stay 0
__device__ float  g_C1[(size_t)N_NODES * C1_LD];  // q|k|(v unused)|qv
__device__ __half g_V [(size_t)N_NODES * 512];    // v in fp16 (written by GEMM epilogue)
__device__ __half g_A2[(size_t)N_NODES * K2];     // [feat_hi | feat_lo], written by attn
__device__ __half g_B2[(size_t)512 * K2];         // [Wout_hi | Wout_hi]
__device__ int    g_idx64;

// ---------------- helpers -----------------------------------------------------
__device__ __forceinline__ uint32_t smem_u32(const void* p) {
    uint32_t a;
    asm("{ .reg .u64 t; cvta.to.shared.u64 t, %1; cvt.u32.u64 %0, t; }" : "=r"(a) : "l"(p));
    return a;
}
__device__ __forceinline__ void cp_async16(uint32_t saddr, const void* g) {
    asm volatile("cp.async.cg.shared.global [%0], [%1], 16;\n" :: "r"(saddr), "l"(g));
}
__device__ __forceinline__ void ldm_x4(uint32_t* r, uint32_t addr) {
    asm volatile("ldmatrix.sync.aligned.m8n8.x4.shared.b16 {%0,%1,%2,%3}, [%4];"
                 : "=r"(r[0]), "=r"(r[1]), "=r"(r[2]), "=r"(r[3]) : "r"(addr));
}
__device__ __forceinline__ void mma16816(float* d, const uint32_t* a, const uint32_t* b) {
    asm volatile("mma.sync.aligned.m16n8k16.row.col.f32.f16.f16.f32 "
                 "{%0,%1,%2,%3}, {%4,%5,%6,%7}, {%8,%9}, {%0,%1,%2,%3};"
                 : "+f"(d[0]), "+f"(d[1]), "+f"(d[2]), "+f"(d[3])
                 : "r"(a[0]), "r"(a[1]), "r"(a[2]), "r"(a[3]), "r"(b[0]), "r"(b[1]));
}
__device__ __forceinline__ uint32_t sw128(uint32_t off) {  // 128B-row swizzle
    return off ^ ((off >> 3) & 0x70);
}

__device__ __forceinline__ int ldidx(const int* __restrict__ p, int i, int is64) {
    return is64 ? p[(size_t)2*i] : p[i];
}

// ---------------- split conversions --------------------------------------------
__device__ __forceinline__ void split_f16(float v, __half& hi, __half& lo) {
    hi = __float2half(v);
    lo = __float2half(v - __half2float(hi));
}

// ---------------- merged conversion kernel (one launch) ------------------------
#define CX_BLOCKS 16384
#define CW_BLOCKS 3120
#define CO_BLOCKS 1088
#define CONV_BLOCKS (CX_BLOCKS + CW_BLOCKS + CO_BLOCKS)

__global__ __launch_bounds__(256) void conv_all(
        const float* __restrict__ x,
        const float* __restrict__ Wq, const float* __restrict__ Wk,
        const float* __restrict__ Wv, const float* __restrict__ Wqv,
        const float* __restrict__ Wout, const int* __restrict__ ci)
{
    int b = blockIdx.x;
    if (b < CX_BLOCKS) {
        int idx = b * 256 + threadIdx.x;
        if (idx >= N_NODES * D_DIM) return;
        int m = idx >> 9, k = idx & 511;
        __half hi, lo; split_f16(x[idx], hi, lo);
        __half* r = g_A1 + (size_t)m * K1;
        r[k] = hi; r[512 + k] = lo;
    } else if (b < CX_BLOCKS + CW_BLOCKS) {
        if (b == CX_BLOCKS && threadIdx.x == 0) {   // detect index dtype
            int all0 = 1;
            #pragma unroll
            for (int i = 0; i < 64; i++)
                if (ci[2*i + 1] != 0) { all0 = 0; break; }
            g_idx64 = all0;
        }
        int idx = (b - CX_BLOCKS) * 256 + threadIdx.x;
        if (idx >= 1560 * 512) return;
        int n = idx / 512, k = idx % 512;
        float v;
        if      (n < 512)  v = Wq[n * 512 + k] * 0.125f;      // fold 1/sqrt(dk)
        else if (n < 1024) v = Wk[(n - 512) * 512 + k];
        else if (n < 1536) v = Wv[(n - 1024) * 512 + k];
        else               v = Wqv[(n - 1536) * 512 + k];
        __half hi = __float2half(v);
        __half* r = g_B1 + (size_t)n * K1;
        r[k] = hi; r[512 + k] = hi;
    } else {
        int idx = (b - CX_BLOCKS - CW_BLOCKS) * 256 + threadIdx.x;
        if (idx >= 512 * 544) return;
        int n = idx / 544, k = idx % 544;
        __half hi = __float2half(Wout[(size_t)n * FEAT_COLS + k]);
        __half* r = g_B2 + (size_t)n * K2;
        r[k] = hi; r[544 + k] = hi;
    }
}

// ---------------- fp16 HMMA GEMM: C[M,Nc] = A[M,K] @ B[Nc,K]^T (+bias) --------
// grid = (Nc/128, M/128), 128 threads (4 warps, 2x2 of 64x64 tiles), K % 64 == 0.
// 3-stage cp.async pipeline (BK=64) + register-level fragment double-buffering.
// VOUT: CTAs with n0 in [1024,1536) write fp16 to vout (proj v-columns path).
template<bool VOUT>
__global__ __launch_bounds__(128, 2)
void gemm_f16_mma(const __half* __restrict__ A, const __half* __restrict__ B,
                  float* __restrict__ C, int K, int ldc, const float* __restrict__ bias,
                  __half* __restrict__ vout)
{
    extern __shared__ __align__(1024) __half smem[];
    __half* sA = smem;                                 // STAGES * 128*64
    __half* sB = smem + STAGES * 128 * BK;

    const int tid = threadIdx.x, wid = tid >> 5, lane = tid & 31;
    const int m0 = blockIdx.y * 128, n0 = blockIdx.x * 128;
    const int wm = wid & 1, wn = wid >> 1;             // warp tile 64(m) x 64(n)

    float acc[4][8][4];
    #pragma unroll
    for (int i = 0; i < 4; i++)
        #pragma unroll
        for (int j = 0; j < 8; j++)
            #pragma unroll
            for (int t = 0; t < 4; t++) acc[i][j][t] = 0.f;

    const uint32_t saA = smem_u32(sA), saB = smem_u32(sB);

    auto fill = [&](int kt) {
        const int st = kt % STAGES;
        const uint32_t da = saA + st * STAGE_BYTES;
        const uint32_t db = saB + st * STAGE_BYTES;
        const int k0 = kt * BK;
        #pragma unroll
        for (int i = 0; i < 8; i++) {
            int idx = tid + i * 128;
            int r = idx >> 3, c = idx & 7;
            uint32_t sw = sw128((uint32_t)(r * 128 + c * 16));
            cp_async16(da + sw, A + (size_t)(m0 + r) * K + k0 + c * 8);
        }
        #pragma unroll
        for (int i = 0; i < 8; i++) {
            int idx = tid + i * 128;
            int r = idx >> 3, c = idx & 7;
            uint32_t sw = sw128((uint32_t)(r * 128 + c * 16));
            cp_async16(db + sw, B + (size_t)(n0 + r) * K + k0 + c * 8);
        }
        asm volatile("cp.async.commit_group;\n" ::: "memory");
    };

    // per-lane ldmatrix row offsets (byte row stride = 128)
    const uint32_t a_row  = (uint32_t)(wm * 64 + (lane & 15));                     // + mt*16
    const uint32_t a_kh   = (uint32_t)((lane >> 4) * 16);                          // byte k-half
    const uint32_t b_row  = (uint32_t)(wn * 64 + ((lane >> 4) << 3) + (lane & 7)); // + np*16
    const uint32_t b_kh   = (uint32_t)(((lane >> 3) & 1) * 16);

    const int KT = K / BK;

    #pragma unroll
    for (int kt = 0; kt < STAGES - 1; kt++) {
        if (kt < KT) fill(kt);
        else asm volatile("cp.async.commit_group;\n" ::: "memory");
    }

    uint32_t af[2][4][4], bf[2][4][4];

    for (int kt = 0; kt < KT; kt++) {
        asm volatile("cp.async.wait_group %0;\n" :: "n"(STAGES - 2) : "memory");
        __syncthreads();

        if (kt + STAGES - 1 < KT) fill(kt + STAGES - 1);
        else asm volatile("cp.async.commit_group;\n" ::: "memory");

        const int st = kt % STAGES;
        const uint32_t da = saA + st * STAGE_BYTES;
        const uint32_t db = saB + st * STAGE_BYTES;

        // load fragments for k16 = 0
        #pragma unroll
        for (int mt = 0; mt < 4; mt++)
            ldm_x4(af[0][mt], da + sw128((a_row + mt * 16) * 128 + a_kh));
        #pragma unroll
        for (int np = 0; np < 4; np++)
            ldm_x4(bf[0][np], db + sw128((b_row + np * 16) * 128 + b_kh));

        #pragma unroll
        for (int k16 = 0; k16 < BK / 16; k16++) {
            const int cur = k16 & 1;
            if (k16 + 1 < BK / 16) {                   // prefetch next k16 frags
                const int nxt = cur ^ 1;
                uint32_t ko = (uint32_t)((k16 + 1) * 32);
                #pragma unroll
                for (int mt = 0; mt < 4; mt++)
                    ldm_x4(af[nxt][mt], da + sw128((a_row + mt * 16) * 128 + a_kh + ko));
                #pragma unroll
                for (int np = 0; np < 4; np++)
                    ldm_x4(bf[nxt][np], db + sw128((b_row + np * 16) * 128 + b_kh + ko));
            }
            #pragma unroll
            for (int mt = 0; mt < 4; mt++)
                #pragma unroll
                for (int nt = 0; nt < 8; nt++)
                    mma16816(acc[mt][nt], af[cur][mt], &bf[cur][nt >> 1][(nt & 1) * 2]);
        }
    }

    // epilogue
    const int er = lane >> 2, ec = (lane & 3) * 2;
    if (VOUT && n0 >= 1024 && n0 < 1536) {             // v columns -> fp16 buffer
        #pragma unroll
        for (int mt = 0; mt < 4; mt++) {
            #pragma unroll
            for (int nt = 0; nt < 8; nt++) {
                int row  = m0 + wm * 64 + mt * 16 + er;
                int vcol = n0 - 1024 + wn * 64 + nt * 8 + ec;
                __half2 v0 = __floats2half2_rn(acc[mt][nt][0], acc[mt][nt][1]);
                __half2 v1 = __floats2half2_rn(acc[mt][nt][2], acc[mt][nt][3]);
                *(__half2*)(vout + (size_t)row * 512 + vcol)       = v0;
                *(__half2*)(vout + (size_t)(row + 8) * 512 + vcol) = v1;
            }
        }
    } else {
        #pragma unroll
        for (int mt = 0; mt < 4; mt++) {
            #pragma unroll
            for (int nt = 0; nt < 8; nt++) {
                int row = m0 + wm * 64 + mt * 16 + er;
                int col = n0 + wn * 64 + nt * 8 + ec;
                float b0 = bias ? bias[col] : 0.f;
                float b1 = bias ? bias[col + 1] : 0.f;
                float2 v0 = { acc[mt][nt][0] + b0, acc[mt][nt][1] + b1 };
                float2 v1 = { acc[mt][nt][2] + b0, acc[mt][nt][3] + b1 };
                *(float2*)(C + (size_t)row * ldc + col)       = v0;
                *(float2*)(C + (size_t)(row + 8) * ldc + col) = v1;
            }
        }
    }
}

// ---------------- per-row attention (block = row, warp = head) -----------------
__device__ __forceinline__ void store_pair2(__half* r, int k, float x, float y) {
    __half hx, lx, hy, ly;
    split_f16(x, hx, lx); split_f16(y, hy, ly);
    __half2 h2, l2;
    h2.x = hx; h2.y = hy; l2.x = lx; l2.y = ly;
    *(__half2*)(r + k)       = h2;
    *(__half2*)(r + 544 + k) = l2;
}

__global__ __launch_bounds__(256)
void attn_kernel(const float* __restrict__ C1, const __half* __restrict__ V,
                 const int* __restrict__ col_index, const int* __restrict__ to_col,
                 const float* __restrict__ att_bias, const float* __restrict__ dist,
                 const float* __restrict__ pos, const float* __restrict__ col_pos)
{
    __shared__ int   s_cn[DEG];
    __shared__ float s_cp[DEG][3];
    __shared__ float s_rel[DEG][3];
    __shared__ float s_de[DEG];
    __shared__ float s_att[H_HEADS][DEG];

    int row = blockIdx.x;
    int tid = threadIdx.x;

    if (tid < DEG) {
        int is64 = g_idx64;
        int e  = row * DEG + tid;
        int c  = ldidx(col_index, e, is64);
        int cn = ldidx(to_col,   c, is64);
        s_cn[tid] = cn;
        float px = pos[row*3+0], py = pos[row*3+1], pz = pos[row*3+2];
        float cx = col_pos[c*3+0], cy = col_pos[c*3+1], cz = col_pos[c*3+2];
        s_cp[tid][0]  = cx;      s_cp[tid][1]  = cy;      s_cp[tid][2]  = cz;
        s_rel[tid][0] = cx - px; s_rel[tid][1] = cy - py; s_rel[tid][2] = cz - pz;
        float d0 = dist[e];
        s_de[tid] = (d0 == 0.f) ? INFINITY : d0;
    }
    __syncthreads();

    int h = tid >> 5, lane = tid & 31;
    __half* a2row = g_A2 + (size_t)row * K2;

    const float4* q4 = (const float4*)(C1 + (size_t)row * C1_LD + h * DKV);
    float4 qf = q4[lane & 15];
    const float* qvp = C1 + (size_t)row * C1_LD + QV_OFF + h * 3;
    float a0 = qvp[0], a1 = qvp[1], a2 = qvp[2];

    float mylogit = -INFINITY;
    #pragma unroll
    for (int i = 0; i < 8; i++) {
        int j = 2 * i + (lane >> 4);
        const float4* kp4 = (const float4*)(C1 + (size_t)s_cn[j] * C1_LD + 512 + h * DKV);
        float4 kf = kp4[lane & 15];
        float p = qf.x*kf.x + qf.y*kf.y + qf.z*kf.z + qf.w*kf.w;
        #pragma unroll
        for (int o = 8; o; o >>= 1) p += __shfl_xor_sync(0xffffffffu, p, o);
        float tmp = __shfl_sync(0xffffffffu, p, (lane & 1) << 4);
        if ((lane >> 1) == i) mylogit = tmp;
    }
    if (lane < DEG) {
        float ang = a0*s_rel[lane][0] + a1*s_rel[lane][1] + a2*s_rel[lane][2];
        mylogit += att_bias[(size_t)h * E_EDGES + row * DEG + lane] + ang / s_de[lane];
    }

    float m = mylogit;
    #pragma unroll
    for (int o = 16; o; o >>= 1) m = fmaxf(m, __shfl_xor_sync(0xffffffffu, m, o));
    float pe = (lane < DEG) ? expf(mylogit - m) : 0.f;
    float ss = pe;
    #pragma unroll
    for (int o = 16; o; o >>= 1) ss += __shfl_xor_sync(0xffffffffu, ss, o);
    float att  = pe / ss;
    float natt = (lane < DEG) ? att / s_de[lane] : 0.f;
    if (lane < DEG) s_att[h][lane] = att;

    float d0v = (lane < DEG) ? natt * s_cp[lane][0] : 0.f;
    float d1v = (lane < DEG) ? natt * s_cp[lane][1] : 0.f;
    float d2v = (lane < DEG) ? natt * s_cp[lane][2] : 0.f;
    float avg = natt;
    #pragma unroll
    for (int o = 16; o; o >>= 1) {
        d0v += __shfl_xor_sync(0xffffffffu, d0v, o);
        d1v += __shfl_xor_sync(0xffffffffu, d1v, o);
        d2v += __shfl_xor_sync(0xffffffffu, d2v, o);
        avg += __shfl_xor_sync(0xffffffffu, avg, o);
    }
    int kb = h * (DKV + 4);
    if (lane == 0) {
        float px = pos[row*3+0], py = pos[row*3+1], pz = pos[row*3+2];
        float dx = d0v - avg*px, dy = d1v - avg*py, dz = d2v - avg*pz;
        float nrm = sqrtf(dx*dx + dy*dy + dz*dz);
        float inv = 1.f / fmaxf(nrm, 1e-12f);
        store_pair2(a2row, kb + DKV + 0, dx*inv, dy*inv);
        store_pair2(a2row, kb + DKV + 2, dz*inv, avg);
    }
    __syncwarp();

    float2 acc2 = {0.f, 0.f};
    #pragma unroll
    for (int j = 0; j < DEG; j++) {
        const __half2* vp2 = (const __half2*)(V + (size_t)s_cn[j] * 512 + h * DKV);
        float2 v = __half22float2(vp2[lane]);
        float a = s_att[h][j];
        acc2.x += a * v.x;
        acc2.y += a * v.y;
    }
    store_pair2(a2row, kb + 2 * lane, acc2.x, acc2.y);
}

// ---------------- launch --------------------------------------------------------
extern "C" void kernel_launch(void* const* d_in, const int* in_sizes, int n_in,
                              void* d_out, int out_size)
{
    const float* x         = (const float*)d_in[0];
    const int*   col_index = (const int*)  d_in[2];
    const int*   to_col    = (const int*)  d_in[3];
    const float* att_bias  = (const float*)d_in[4];
    const float* dist      = (const float*)d_in[5];
    const float* pos       = (const float*)d_in[6];
    const float* col_pos   = (const float*)d_in[7];
    const float* Wq        = (const float*)d_in[8];
    const float* Wqv       = (const float*)d_in[9];
    const float* Wk        = (const float*)d_in[10];
    const float* Wv        = (const float*)d_in[11];
    const float* Wout      = (const float*)d_in[12];
    const float* bout      = (const float*)d_in[13];
    float*       out       = (float*)d_out;

    void *pA1, *pB1, *pC1, *pV, *pA2, *pB2;
    cudaGetSymbolAddress(&pA1, g_A1);
    cudaGetSymbolAddress(&pB1, g_B1);
    cudaGetSymbolAddress(&pC1, g_C1);
    cudaGetSymbolAddress(&pV,  g_V);
    cudaGetSymbolAddress(&pA2, g_A2);
    cudaGetSymbolAddress(&pB2, g_B2);

    const int SMEM = STAGES * 2 * STAGE_BYTES;     // 3*2*16384 = 98304
    cudaFuncSetAttribute(gemm_f16_mma<true>,  cudaFuncAttributeMaxDynamicSharedMemorySize, SMEM);
    cudaFuncSetAttribute(gemm_f16_mma<false>, cudaFuncAttributeMaxDynamicSharedMemorySize, SMEM);

    conv_all<<<CONV_BLOCKS, 256>>>(x, Wq, Wk, Wv, Wqv, Wout, col_index);

    dim3 g1(B1_ROWS / 128, N_NODES / 128);     // 13 x 64
    gemm_f16_mma<true><<<g1, 128, SMEM>>>((const __half*)pA1, (const __half*)pB1,
                                          (float*)pC1, K1, C1_LD, nullptr, (__half*)pV);

    attn_kernel<<<N_NODES, 256>>>((const float*)pC1, (const __half*)pV,
                                  col_index, to_col, att_bias, dist, pos, col_pos);

    dim3 g2(512 / 128, N_NODES / 128);         // 4 x 64
    gemm_f16_mma<false><<<g2, 128, SMEM>>>((const __half*)pA2, (const __half*)pB2,
                                           out, K2, 512, bout, nullptr);
}

// round 11
// speedup vs baseline: 1.1254x; 1.1254x over previous
#include <cuda_runtime.h>
#include <cuda_fp16.h>
#include <math.h>
#include <stdint.h>

#define N_NODES 8192
#define D_DIM   512
#define H_HEADS 8
#define DKV     64
#define DEG     16
#define E_EDGES (N_NODES*DEG)          // 131072
#define FEAT_COLS 544

// GEMM geometry
#define K1 1024            // proj: 2*512 (split-fp16 x)
#define B1_ROWS 1664       // 512(q)+512(k)+512(v)+24(qv) = 1560, padded to 13*128
#define C1_LD 1664
#define K2 576             // out: 544 + 32 zero pad (single-fp16 feat)
#define QV_OFF 1536
#define STAGES 3
#define BK 64
#define STAGE_BYTES (128 * BK * 2)     // 16384 per operand per stage

// ---------------- device-global scratch (no allocations allowed) ------------
__device__ __half g_A1[(size_t)N_NODES * K1];     // [x_hi | x_lo]
__device__ __half g_B1[(size_t)B1_ROWS * K1];     // [W_hi | W_hi], pad rows stay 0
__device__ float  g_C1[(size_t)N_NODES * C1_LD];  // q|k|(v unused)|qv
__device__ __half g_V [(size_t)N_NODES * 512];    // v in fp16 (written by GEMM epilogue)
__device__ __half g_A2[(size_t)N_NODES * K2];     // feat fp16 (cols 544.. stay 0)
__device__ __half g_B2[(size_t)512 * K2];         // Wout fp16 (cols 544.. stay 0)
__device__ int    g_idx64;

// ---------------- helpers -----------------------------------------------------
__device__ __forceinline__ uint32_t smem_u32(const void* p) {
    uint32_t a;
    asm("{ .reg .u64 t; cvta.to.shared.u64 t, %1; cvt.u32.u64 %0, t; }" : "=r"(a) : "l"(p));
    return a;
}
__device__ __forceinline__ void cp_async16(uint32_t saddr, const void* g) {
    asm volatile("cp.async.cg.shared.global [%0], [%1], 16;\n" :: "r"(saddr), "l"(g));
}
__device__ __forceinline__ void ldm_x4(uint32_t* r, uint32_t addr) {
    asm volatile("ldmatrix.sync.aligned.m8n8.x4.shared.b16 {%0,%1,%2,%3}, [%4];"
                 : "=r"(r[0]), "=r"(r[1]), "=r"(r[2]), "=r"(r[3]) : "r"(addr));
}
__device__ __forceinline__ void mma16816(float* d, const uint32_t* a, const uint32_t* b) {
    asm volatile("mma.sync.aligned.m16n8k16.row.col.f32.f16.f16.f32 "
                 "{%0,%1,%2,%3}, {%4,%5,%6,%7}, {%8,%9}, {%0,%1,%2,%3};"
                 : "+f"(d[0]), "+f"(d[1]), "+f"(d[2]), "+f"(d[3])
                 : "r"(a[0]), "r"(a[1]), "r"(a[2]), "r"(a[3]), "r"(b[0]), "r"(b[1]));
}
__device__ __forceinline__ uint32_t sw128(uint32_t off) {  // 128B-row swizzle
    return off ^ ((off >> 3) & 0x70);
}

__device__ __forceinline__ int ldidx(const int* __restrict__ p, int i, int is64) {
    return is64 ? p[(size_t)2*i] : p[i];
}

// ---------------- split conversions --------------------------------------------
__device__ __forceinline__ void split_f16(float v, __half& hi, __half& lo) {
    hi = __float2half(v);
    lo = __float2half(v - __half2float(hi));
}

// ---------------- merged conversion kernel (one launch) ------------------------
#define CX_BLOCKS 16384
#define CW_BLOCKS 3120
#define CO_BLOCKS 1088
#define CONV_BLOCKS (CX_BLOCKS + CW_BLOCKS + CO_BLOCKS)

__global__ __launch_bounds__(256) void conv_all(
        const float* __restrict__ x,
        const float* __restrict__ Wq, const float* __restrict__ Wk,
        const float* __restrict__ Wv, const float* __restrict__ Wqv,
        const float* __restrict__ Wout, const int* __restrict__ ci)
{
    int b = blockIdx.x;
    if (b < CX_BLOCKS) {
        int idx = b * 256 + threadIdx.x;
        if (idx >= N_NODES * D_DIM) return;
        int m = idx >> 9, k = idx & 511;
        __half hi, lo; split_f16(x[idx], hi, lo);
        __half* r = g_A1 + (size_t)m * K1;
        r[k] = hi; r[512 + k] = lo;
    } else if (b < CX_BLOCKS + CW_BLOCKS) {
        if (b == CX_BLOCKS && threadIdx.x == 0) {   // detect index dtype
            int all0 = 1;
            #pragma unroll
            for (int i = 0; i < 64; i++)
                if (ci[2*i + 1] != 0) { all0 = 0; break; }
            g_idx64 = all0;
        }
        int idx = (b - CX_BLOCKS) * 256 + threadIdx.x;
        if (idx >= 1560 * 512) return;
        int n = idx / 512, k = idx % 512;
        float v;
        if      (n < 512)  v = Wq[n * 512 + k] * 0.125f;      // fold 1/sqrt(dk)
        else if (n < 1024) v = Wk[(n - 512) * 512 + k];
        else if (n < 1536) v = Wv[(n - 1024) * 512 + k];
        else               v = Wqv[(n - 1536) * 512 + k];
        __half hi = __float2half(v);
        __half* r = g_B1 + (size_t)n * K1;
        r[k] = hi; r[512 + k] = hi;
    } else {
        int idx = (b - CX_BLOCKS - CW_BLOCKS) * 256 + threadIdx.x;
        if (idx >= 512 * 544) return;
        int n = idx / 544, k = idx % 544;
        g_B2[(size_t)n * K2 + k] = __float2half(Wout[(size_t)n * FEAT_COLS + k]);
    }
}

// ---------------- fp16 HMMA GEMM: C[M,Nc] = A[M,K] @ B[Nc,K]^T (+bias) --------
// grid = (Nc/128, M/128), 128 threads (4 warps, 2x2 of 64x64 tiles), K % 64 == 0.
// 3-stage cp.async pipeline (BK=64), 2 CTAs/SM.
// VOUT: CTAs with n0 in [1024,1536) write fp16 to vout (proj v-columns path).
template<bool VOUT>
__global__ __launch_bounds__(128, 2)
void gemm_f16_mma(const __half* __restrict__ A, const __half* __restrict__ B,
                  float* __restrict__ C, int K, int ldc, const float* __restrict__ bias,
                  __half* __restrict__ vout)
{
    extern __shared__ __align__(1024) __half smem[];
    __half* sA = smem;                                 // STAGES * 128*64
    __half* sB = smem + STAGES * 128 * BK;

    const int tid = threadIdx.x, wid = tid >> 5, lane = tid & 31;
    const int m0 = blockIdx.y * 128, n0 = blockIdx.x * 128;
    const int wm = wid & 1, wn = wid >> 1;             // warp tile 64(m) x 64(n)

    float acc[4][8][4];
    #pragma unroll
    for (int i = 0; i < 4; i++)
        #pragma unroll
        for (int j = 0; j < 8; j++)
            #pragma unroll
            for (int t = 0; t < 4; t++) acc[i][j][t] = 0.f;

    const uint32_t saA = smem_u32(sA), saB = smem_u32(sB);

    auto fill = [&](int kt) {
        const int st = kt % STAGES;
        const uint32_t da = saA + st * STAGE_BYTES;
        const uint32_t db = saB + st * STAGE_BYTES;
        const int k0 = kt * BK;
        #pragma unroll
        for (int i = 0; i < 8; i++) {
            int idx = tid + i * 128;
            int r = idx >> 3, c = idx & 7;
            uint32_t sw = sw128((uint32_t)(r * 128 + c * 16));
            cp_async16(da + sw, A + (size_t)(m0 + r) * K + k0 + c * 8);
        }
        #pragma unroll
        for (int i = 0; i < 8; i++) {
            int idx = tid + i * 128;
            int r = idx >> 3, c = idx & 7;
            uint32_t sw = sw128((uint32_t)(r * 128 + c * 16));
            cp_async16(db + sw, B + (size_t)(n0 + r) * K + k0 + c * 8);
        }
        asm volatile("cp.async.commit_group;\n" ::: "memory");
    };

    // per-lane ldmatrix row offsets (byte row stride = 128)
    const uint32_t a_row  = (uint32_t)(wm * 64 + (lane & 15));                     // + mt*16
    const uint32_t a_kh   = (uint32_t)((lane >> 4) * 16);                          // byte k-half
    const uint32_t b_row  = (uint32_t)(wn * 64 + ((lane >> 4) << 3) + (lane & 7)); // + np*16
    const uint32_t b_kh   = (uint32_t)(((lane >> 3) & 1) * 16);

    const int KT = K / BK;

    #pragma unroll
    for (int kt = 0; kt < STAGES - 1; kt++) {
        if (kt < KT) fill(kt);
        else asm volatile("cp.async.commit_group;\n" ::: "memory");
    }

    for (int kt = 0; kt < KT; kt++) {
        asm volatile("cp.async.wait_group %0;\n" :: "n"(STAGES - 2) : "memory");
        __syncthreads();

        if (kt + STAGES - 1 < KT) fill(kt + STAGES - 1);
        else asm volatile("cp.async.commit_group;\n" ::: "memory");

        const int st = kt % STAGES;
        const uint32_t da = saA + st * STAGE_BYTES;
        const uint32_t db = saB + st * STAGE_BYTES;
        #pragma unroll
        for (int k16 = 0; k16 < BK / 16; k16++) {
            uint32_t af[4][4], bf[4][4];
            #pragma unroll
            for (int mt = 0; mt < 4; mt++) {
                uint32_t off = (a_row + mt * 16) * 128 + a_kh + k16 * 32;
                ldm_x4(af[mt], da + sw128(off));
            }
            #pragma unroll
            for (int np = 0; np < 4; np++) {
                uint32_t off = (b_row + np * 16) * 128 + b_kh + k16 * 32;
                ldm_x4(bf[np], db + sw128(off));
            }
            #pragma unroll
            for (int mt = 0; mt < 4; mt++)
                #pragma unroll
                for (int nt = 0; nt < 8; nt++)
                    mma16816(acc[mt][nt], af[mt], &bf[nt >> 1][(nt & 1) * 2]);
        }
    }

    // epilogue
    const int er = lane >> 2, ec = (lane & 3) * 2;
    if (VOUT && n0 >= 1024 && n0 < 1536) {             // v columns -> fp16 buffer
        #pragma unroll
        for (int mt = 0; mt < 4; mt++) {
            #pragma unroll
            for (int nt = 0; nt < 8; nt++) {
                int row  = m0 + wm * 64 + mt * 16 + er;
                int vcol = n0 - 1024 + wn * 64 + nt * 8 + ec;
                __half2 v0 = __floats2half2_rn(acc[mt][nt][0], acc[mt][nt][1]);
                __half2 v1 = __floats2half2_rn(acc[mt][nt][2], acc[mt][nt][3]);
                *(__half2*)(vout + (size_t)row * 512 + vcol)       = v0;
                *(__half2*)(vout + (size_t)(row + 8) * 512 + vcol) = v1;
            }
        }
    } else {
        #pragma unroll
        for (int mt = 0; mt < 4; mt++) {
            #pragma unroll
            for (int nt = 0; nt < 8; nt++) {
                int row = m0 + wm * 64 + mt * 16 + er;
                int col = n0 + wn * 64 + nt * 8 + ec;
                float b0 = bias ? bias[col] : 0.f;
                float b1 = bias ? bias[col + 1] : 0.f;
                float2 v0 = { acc[mt][nt][0] + b0, acc[mt][nt][1] + b1 };
                float2 v1 = { acc[mt][nt][2] + b0, acc[mt][nt][3] + b1 };
                *(float2*)(C + (size_t)row * ldc + col)       = v0;
                *(float2*)(C + (size_t)(row + 8) * ldc + col) = v1;
            }
        }
    }
}

// ---------------- per-row attention (block = row, warp = head) -----------------
// Writes single-fp16 feat directly into g_A2 (row stride K2=576; pad cols stay 0).
__global__ __launch_bounds__(256)
void attn_kernel(const float* __restrict__ C1, const __half* __restrict__ V,
                 const int* __restrict__ col_index, const int* __restrict__ to_col,
                 const float* __restrict__ att_bias, const float* __restrict__ dist,
                 const float* __restrict__ pos, const float* __restrict__ col_pos)
{
    __shared__ int   s_cn[DEG];
    __shared__ float s_cp[DEG][3];
    __shared__ float s_rel[DEG][3];
    __shared__ float s_de[DEG];
    __shared__ float s_att[H_HEADS][DEG];

    int row = blockIdx.x;
    int tid = threadIdx.x;

    if (tid < DEG) {
        int is64 = g_idx64;
        int e  = row * DEG + tid;
        int c  = ldidx(col_index, e, is64);
        int cn = ldidx(to_col,   c, is64);
        s_cn[tid] = cn;
        float px = pos[row*3+0], py = pos[row*3+1], pz = pos[row*3+2];
        float cx = col_pos[c*3+0], cy = col_pos[c*3+1], cz = col_pos[c*3+2];
        s_cp[tid][0]  = cx;      s_cp[tid][1]  = cy;      s_cp[tid][2]  = cz;
        s_rel[tid][0] = cx - px; s_rel[tid][1] = cy - py; s_rel[tid][2] = cz - pz;
        float d0 = dist[e];
        s_de[tid] = (d0 == 0.f) ? INFINITY : d0;
    }
    __syncthreads();

    int h = tid >> 5, lane = tid & 31;
    __half* a2row = g_A2 + (size_t)row * K2;

    const float4* q4 = (const float4*)(C1 + (size_t)row * C1_LD + h * DKV);
    float4 qf = q4[lane & 15];
    const float* qvp = C1 + (size_t)row * C1_LD + QV_OFF + h * 3;
    float a0 = qvp[0], a1 = qvp[1], a2 = qvp[2];

    // logits: half-warp per edge, 2 edges per iteration, float4 dot products
    float mylogit = -INFINITY;
    #pragma unroll
    for (int i = 0; i < 8; i++) {
        int j = 2 * i + (lane >> 4);
        const float4* kp4 = (const float4*)(C1 + (size_t)s_cn[j] * C1_LD + 512 + h * DKV);
        float4 kf = kp4[lane & 15];
        float p = qf.x*kf.x + qf.y*kf.y + qf.z*kf.z + qf.w*kf.w;
        #pragma unroll
        for (int o = 8; o; o >>= 1) p += __shfl_xor_sync(0xffffffffu, p, o);
        float tmp = __shfl_sync(0xffffffffu, p, (lane & 1) << 4);
        if ((lane >> 1) == i) mylogit = tmp;
    }
    if (lane < DEG) {
        float ang = a0*s_rel[lane][0] + a1*s_rel[lane][1] + a2*s_rel[lane][2];
        mylogit += att_bias[(size_t)h * E_EDGES + row * DEG + lane] + ang / s_de[lane];
    }

    // softmax over lanes 0..15
    float m = mylogit;
    #pragma unroll
    for (int o = 16; o; o >>= 1) m = fmaxf(m, __shfl_xor_sync(0xffffffffu, m, o));
    float pe = (lane < DEG) ? expf(mylogit - m) : 0.f;
    float ss = pe;
    #pragma unroll
    for (int o = 16; o; o >>= 1) ss += __shfl_xor_sync(0xffffffffu, ss, o);
    float att  = pe / ss;
    float natt = (lane < DEG) ? att / s_de[lane] : 0.f;
    if (lane < DEG) s_att[h][lane] = att;

    float d0v = (lane < DEG) ? natt * s_cp[lane][0] : 0.f;
    float d1v = (lane < DEG) ? natt * s_cp[lane][1] : 0.f;
    float d2v = (lane < DEG) ? natt * s_cp[lane][2] : 0.f;
    float avg = natt;
    #pragma unroll
    for (int o = 16; o; o >>= 1) {
        d0v += __shfl_xor_sync(0xffffffffu, d0v, o);
        d1v += __shfl_xor_sync(0xffffffffu, d1v, o);
        d2v += __shfl_xor_sync(0xffffffffu, d2v, o);
        avg += __shfl_xor_sync(0xffffffffu, avg, o);
    }
    int kb = h * (DKV + 4);
    if (lane == 0) {
        float px = pos[row*3+0], py = pos[row*3+1], pz = pos[row*3+2];
        float dx = d0v - avg*px, dy = d1v - avg*py, dz = d2v - avg*pz;
        float nrm = sqrtf(dx*dx + dy*dy + dz*dz);
        float inv = 1.f / fmaxf(nrm, 1e-12f);
        *(__half2*)(a2row + kb + DKV + 0) = __floats2half2_rn(dx*inv, dy*inv);
        *(__half2*)(a2row + kb + DKV + 2) = __floats2half2_rn(dz*inv, avg);
    }
    __syncwarp();

    // y = att @ V (fp16 gather), float2 per lane (dims 2*lane, 2*lane+1)
    float2 acc2 = {0.f, 0.f};
    #pragma unroll
    for (int j = 0; j < DEG; j++) {
        const __half2* vp2 = (const __half2*)(V + (size_t)s_cn[j] * 512 + h * DKV);
        float2 v = __half22float2(vp2[lane]);
        float a = s_att[h][j];
        acc2.x += a * v.x;
        acc2.y += a * v.y;
    }
    *(__half2*)(a2row + kb + 2 * lane) = __floats2half2_rn(acc2.x, acc2.y);
}

// ---------------- launch --------------------------------------------------------
extern "C" void kernel_launch(void* const* d_in, const int* in_sizes, int n_in,
                              void* d_out, int out_size)
{
    const float* x         = (const float*)d_in[0];
    const int*   col_index = (const int*)  d_in[2];
    const int*   to_col    = (const int*)  d_in[3];
    const float* att_bias  = (const float*)d_in[4];
    const float* dist      = (const float*)d_in[5];
    const float* pos       = (const float*)d_in[6];
    const float* col_pos   = (const float*)d_in[7];
    const float* Wq        = (const float*)d_in[8];
    const float* Wqv       = (const float*)d_in[9];
    const float* Wk        = (const float*)d_in[10];
    const float* Wv        = (const float*)d_in[11];
    const float* Wout      = (const float*)d_in[12];
    const float* bout      = (const float*)d_in[13];
    float*       out       = (float*)d_out;

    void *pA1, *pB1, *pC1, *pV, *pA2, *pB2;
    cudaGetSymbolAddress(&pA1, g_A1);
    cudaGetSymbolAddress(&pB1, g_B1);
    cudaGetSymbolAddress(&pC1, g_C1);
    cudaGetSymbolAddress(&pV,  g_V);
    cudaGetSymbolAddress(&pA2, g_A2);
    cudaGetSymbolAddress(&pB2, g_B2);

    const int SMEM = STAGES * 2 * STAGE_BYTES;     // 3*2*16384 = 98304
    cudaFuncSetAttribute(gemm_f16_mma<true>,  cudaFuncAttributeMaxDynamicSharedMemorySize, SMEM);
    cudaFuncSetAttribute(gemm_f16_mma<false>, cudaFuncAttributeMaxDynamicSharedMemorySize, SMEM);

    conv_all<<<CONV_BLOCKS, 256>>>(x, Wq, Wk, Wv, Wqv, Wout, col_index);

    dim3 g1(B1_ROWS / 128, N_NODES / 128);     // 13 x 64
    gemm_f16_mma<true><<<g1, 128, SMEM>>>((const __half*)pA1, (const __half*)pB1,
                                          (float*)pC1, K1, C1_LD, nullptr, (__half*)pV);

    attn_kernel<<<N_NODES, 256>>>((const float*)pC1, (const __half*)pV,
                                  col_index, to_col, att_bias, dist, pos, col_pos);

    dim3 g2(512 / 128, N_NODES / 128);         // 4 x 64
    gemm_f16_mma<false><<<g2, 128, SMEM>>>((const __half*)pA2, (const __half*)pB2,
                                           out, K2, 512, bout, nullptr);
}

// round 12
// speedup vs baseline: 1.2396x; 1.1014x over previous
#include <cuda_runtime.h>
#include <cuda_fp16.h>
#include <math.h>
#include <stdint.h>

#define N_NODES 8192
#define D_DIM   512
#define H_HEADS 8
#define DKV     64
#define DEG     16
#define E_EDGES (N_NODES*DEG)          // 131072
#define FEAT_COLS 544

// GEMM geometry
#define K_QK 1024          // q,k proj: split-fp16 x, K=2*512
#define K_V  512           // v,qv proj: x_hi only
#define QK_LD 1024
#define K2 576             // out: 544 + 32 zero pad (single-fp16 feat)
#define STAGES 3
#define BK 64
#define STAGE_BYTES (128 * BK * 2)     // 16384 per operand per stage

// ---------------- device-global scratch (no allocations allowed) ------------
__device__ __half g_A1[(size_t)N_NODES * K_QK];   // [x_hi | x_lo]
__device__ __half g_B1[(size_t)1024 * K_QK];      // q,k weights: [W_hi | W_hi]
__device__ __half g_Bv[(size_t)640 * K_V];        // v (0-511), qv (512-535), zero pad
__device__ float  g_QK[(size_t)N_NODES * QK_LD];  // q (0-511) | k (512-1023)
__device__ float  g_QV[(size_t)N_NODES * 128];    // qv (cols 0-23 used)
__device__ __half g_V [(size_t)N_NODES * 512];    // v in fp16
__device__ __half g_A2[(size_t)N_NODES * K2];     // feat fp16 (cols 544.. stay 0)
__device__ __half g_B2[(size_t)512 * K2];         // Wout fp16 (cols 544.. stay 0)
__device__ int    g_idx64;

// ---------------- helpers -----------------------------------------------------
__device__ __forceinline__ uint32_t smem_u32(const void* p) {
    uint32_t a;
    asm("{ .reg .u64 t; cvta.to.shared.u64 t, %1; cvt.u32.u64 %0, t; }" : "=r"(a) : "l"(p));
    return a;
}
__device__ __forceinline__ void cp_async16(uint32_t saddr, const void* g) {
    asm volatile("cp.async.cg.shared.global [%0], [%1], 16;\n" :: "r"(saddr), "l"(g));
}
__device__ __forceinline__ void ldm_x4(uint32_t* r, uint32_t addr) {
    asm volatile("ldmatrix.sync.aligned.m8n8.x4.shared.b16 {%0,%1,%2,%3}, [%4];"
                 : "=r"(r[0]), "=r"(r[1]), "=r"(r[2]), "=r"(r[3]) : "r"(addr));
}
__device__ __forceinline__ void mma16816(float* d, const uint32_t* a, const uint32_t* b) {
    asm volatile("mma.sync.aligned.m16n8k16.row.col.f32.f16.f16.f32 "
                 "{%0,%1,%2,%3}, {%4,%5,%6,%7}, {%8,%9}, {%0,%1,%2,%3};"
                 : "+f"(d[0]), "+f"(d[1]), "+f"(d[2]), "+f"(d[3])
                 : "r"(a[0]), "r"(a[1]), "r"(a[2]), "r"(a[3]), "r"(b[0]), "r"(b[1]));
}
__device__ __forceinline__ uint32_t sw128(uint32_t off) {  // 128B-row swizzle
    return off ^ ((off >> 3) & 0x70);
}

__device__ __forceinline__ int ldidx(const int* __restrict__ p, int i, int is64) {
    return is64 ? p[(size_t)2*i] : p[i];
}

// ---------------- split conversions --------------------------------------------
__device__ __forceinline__ void split_f16(float v, __half& hi, __half& lo) {
    hi = __float2half(v);
    lo = __float2half(v - __half2float(hi));
}

// ---------------- merged conversion kernel (one launch) ------------------------
#define CX_BLOCKS 16384
#define CW_BLOCKS 3328
#define CO_BLOCKS 1088
#define CONV_BLOCKS (CX_BLOCKS + CW_BLOCKS + CO_BLOCKS)

__global__ __launch_bounds__(256) void conv_all(
        const float* __restrict__ x,
        const float* __restrict__ Wq, const float* __restrict__ Wk,
        const float* __restrict__ Wv, const float* __restrict__ Wqv,
        const float* __restrict__ Wout, const int* __restrict__ ci)
{
    int b = blockIdx.x;
    if (b < CX_BLOCKS) {
        int idx = b * 256 + threadIdx.x;
        if (idx >= N_NODES * D_DIM) return;
        int m = idx >> 9, k = idx & 511;
        __half hi, lo; split_f16(x[idx], hi, lo);
        __half* r = g_A1 + (size_t)m * K_QK;
        r[k] = hi; r[512 + k] = lo;
    } else if (b < CX_BLOCKS + CW_BLOCKS) {
        if (b == CX_BLOCKS && threadIdx.x == 0) {   // detect index dtype
            int all0 = 1;
            #pragma unroll
            for (int i = 0; i < 64; i++)
                if (ci[2*i + 1] != 0) { all0 = 0; break; }
            g_idx64 = all0;
        }
        int idx = (b - CX_BLOCKS) * 256 + threadIdx.x;
        if (idx >= 1560 * 512) return;
        int n = idx / 512, k = idx % 512;
        if (n < 1024) {                              // q,k -> B1 (split layout)
            float v = (n < 512) ? Wq[n * 512 + k] * 0.125f
                                : Wk[(n - 512) * 512 + k];
            __half hi = __float2half(v);
            __half* r = g_B1 + (size_t)n * K_QK;
            r[k] = hi; r[512 + k] = hi;
        } else {                                     // v, qv -> Bv (single layout)
            int n2 = n - 1024;                       // 0..535
            float v = (n2 < 512) ? Wv[n2 * 512 + k]
                                 : Wqv[(n2 - 512) * 512 + k];
            g_Bv[(size_t)n2 * K_V + k] = __float2half(v);
        }
    } else {
        int idx = (b - CX_BLOCKS - CW_BLOCKS) * 256 + threadIdx.x;
        if (idx >= 512 * 544) return;
        int n = idx / 544, k = idx % 544;
        g_B2[(size_t)n * K2 + k] = __float2half(Wout[(size_t)n * FEAT_COLS + k]);
    }
}

// ---------------- fused projection GEMM ---------------------------------------
// grid = (13, M/128): bx<8 -> qk GEMM (K=1024, fp32 out to g_QK)
//                     bx>=8 -> v/qv GEMM (K=512; v -> fp16 g_V, qv -> fp32 g_QV)
// A row stride is always K_QK (x_hi in first 512 cols).
__global__ __launch_bounds__(128, 2)
void gemm_proj(const __half* __restrict__ A, const __half* __restrict__ B1,
               const __half* __restrict__ Bv)
{
    extern __shared__ __align__(1024) __half smem[];
    __half* sA = smem;
    __half* sB = smem + STAGES * 128 * BK;

    const int tid = threadIdx.x, wid = tid >> 5, lane = tid & 31;
    const bool qk = (blockIdx.x < 8);
    const int m0 = blockIdx.y * 128;
    const int n0 = qk ? blockIdx.x * 128 : (blockIdx.x - 8) * 128;
    const int K  = qk ? K_QK : K_V;
    const __half* B = qk ? B1 : Bv;
    const int wm = wid & 1, wn = wid >> 1;             // warp tile 64(m) x 64(n)

    float acc[4][8][4];
    #pragma unroll
    for (int i = 0; i < 4; i++)
        #pragma unroll
        for (int j = 0; j < 8; j++)
            #pragma unroll
            for (int t = 0; t < 4; t++) acc[i][j][t] = 0.f;

    const uint32_t saA = smem_u32(sA), saB = smem_u32(sB);

    auto fill = [&](int kt) {
        const int st = kt % STAGES;
        const uint32_t da = saA + st * STAGE_BYTES;
        const uint32_t db = saB + st * STAGE_BYTES;
        const int k0 = kt * BK;
        #pragma unroll
        for (int i = 0; i < 8; i++) {
            int idx = tid + i * 128;
            int r = idx >> 3, c = idx & 7;
            uint32_t sw = sw128((uint32_t)(r * 128 + c * 16));
            cp_async16(da + sw, A + (size_t)(m0 + r) * K_QK + k0 + c * 8);
        }
        #pragma unroll
        for (int i = 0; i < 8; i++) {
            int idx = tid + i * 128;
            int r = idx >> 3, c = idx & 7;
            uint32_t sw = sw128((uint32_t)(r * 128 + c * 16));
            cp_async16(db + sw, B + (size_t)(n0 + r) * K + k0 + c * 8);
        }
        asm volatile("cp.async.commit_group;\n" ::: "memory");
    };

    const uint32_t a_row  = (uint32_t)(wm * 64 + (lane & 15));
    const uint32_t a_kh   = (uint32_t)((lane >> 4) * 16);
    const uint32_t b_row  = (uint32_t)(wn * 64 + ((lane >> 4) << 3) + (lane & 7));
    const uint32_t b_kh   = (uint32_t)(((lane >> 3) & 1) * 16);

    const int KT = K / BK;

    #pragma unroll
    for (int kt = 0; kt < STAGES - 1; kt++) {
        if (kt < KT) fill(kt);
        else asm volatile("cp.async.commit_group;\n" ::: "memory");
    }

    for (int kt = 0; kt < KT; kt++) {
        asm volatile("cp.async.wait_group %0;\n" :: "n"(STAGES - 2) : "memory");
        __syncthreads();

        if (kt + STAGES - 1 < KT) fill(kt + STAGES - 1);
        else asm volatile("cp.async.commit_group;\n" ::: "memory");

        const int st = kt % STAGES;
        const uint32_t da = saA + st * STAGE_BYTES;
        const uint32_t db = saB + st * STAGE_BYTES;
        #pragma unroll
        for (int k16 = 0; k16 < BK / 16; k16++) {
            uint32_t af[4][4], bf[4][4];
            #pragma unroll
            for (int mt = 0; mt < 4; mt++) {
                uint32_t off = (a_row + mt * 16) * 128 + a_kh + k16 * 32;
                ldm_x4(af[mt], da + sw128(off));
            }
            #pragma unroll
            for (int np = 0; np < 4; np++) {
                uint32_t off = (b_row + np * 16) * 128 + b_kh + k16 * 32;
                ldm_x4(bf[np], db + sw128(off));
            }
            #pragma unroll
            for (int mt = 0; mt < 4; mt++)
                #pragma unroll
                for (int nt = 0; nt < 8; nt++)
                    mma16816(acc[mt][nt], af[mt], &bf[nt >> 1][(nt & 1) * 2]);
        }
    }

    // epilogue
    const int er = lane >> 2, ec = (lane & 3) * 2;
    if (qk) {                                          // fp32 -> g_QK
        #pragma unroll
        for (int mt = 0; mt < 4; mt++) {
            #pragma unroll
            for (int nt = 0; nt < 8; nt++) {
                int row = m0 + wm * 64 + mt * 16 + er;
                int col = n0 + wn * 64 + nt * 8 + ec;
                float2 v0 = { acc[mt][nt][0], acc[mt][nt][1] };
                float2 v1 = { acc[mt][nt][2], acc[mt][nt][3] };
                *(float2*)(g_QK + (size_t)row * QK_LD + col)       = v0;
                *(float2*)(g_QK + (size_t)(row + 8) * QK_LD + col) = v1;
            }
        }
    } else if (n0 < 512) {                             // fp16 -> g_V
        #pragma unroll
        for (int mt = 0; mt < 4; mt++) {
            #pragma unroll
            for (int nt = 0; nt < 8; nt++) {
                int row  = m0 + wm * 64 + mt * 16 + er;
                int vcol = n0 + wn * 64 + nt * 8 + ec;
                __half2 v0 = __floats2half2_rn(acc[mt][nt][0], acc[mt][nt][1]);
                __half2 v1 = __floats2half2_rn(acc[mt][nt][2], acc[mt][nt][3]);
                *(__half2*)(g_V + (size_t)row * 512 + vcol)       = v0;
                *(__half2*)(g_V + (size_t)(row + 8) * 512 + vcol) = v1;
            }
        }
    } else {                                           // fp32 -> g_QV (128 cols)
        #pragma unroll
        for (int mt = 0; mt < 4; mt++) {
            #pragma unroll
            for (int nt = 0; nt < 8; nt++) {
                int row = m0 + wm * 64 + mt * 16 + er;
                int col = wn * 64 + nt * 8 + ec;       // n0==512 -> local col
                float2 v0 = { acc[mt][nt][0], acc[mt][nt][1] };
                float2 v1 = { acc[mt][nt][2], acc[mt][nt][3] };
                *(float2*)(g_QV + (size_t)row * 128 + col)       = v0;
                *(float2*)(g_QV + (size_t)(row + 8) * 128 + col) = v1;
            }
        }
    }
}

// ---------------- output GEMM: out = A2 @ B2^T + bout --------------------------
__global__ __launch_bounds__(128, 2)
void gemm_out(const __half* __restrict__ A, const __half* __restrict__ B,
              float* __restrict__ C, const float* __restrict__ bias)
{
    extern __shared__ __align__(1024) __half smem[];
    __half* sA = smem;
    __half* sB = smem + STAGES * 128 * BK;

    const int tid = threadIdx.x, wid = tid >> 5, lane = tid & 31;
    const int m0 = blockIdx.y * 128, n0 = blockIdx.x * 128;
    const int wm = wid & 1, wn = wid >> 1;

    float acc[4][8][4];
    #pragma unroll
    for (int i = 0; i < 4; i++)
        #pragma unroll
        for (int j = 0; j < 8; j++)
            #pragma unroll
            for (int t = 0; t < 4; t++) acc[i][j][t] = 0.f;

    const uint32_t saA = smem_u32(sA), saB = smem_u32(sB);

    auto fill = [&](int kt) {
        const int st = kt % STAGES;
        const uint32_t da = saA + st * STAGE_BYTES;
        const uint32_t db = saB + st * STAGE_BYTES;
        const int k0 = kt * BK;
        #pragma unroll
        for (int i = 0; i < 8; i++) {
            int idx = tid + i * 128;
            int r = idx >> 3, c = idx & 7;
            uint32_t sw = sw128((uint32_t)(r * 128 + c * 16));
            cp_async16(da + sw, A + (size_t)(m0 + r) * K2 + k0 + c * 8);
        }
        #pragma unroll
        for (int i = 0; i < 8; i++) {
            int idx = tid + i * 128;
            int r = idx >> 3, c = idx & 7;
            uint32_t sw = sw128((uint32_t)(r * 128 + c * 16));
            cp_async16(db + sw, B + (size_t)(n0 + r) * K2 + k0 + c * 8);
        }
        asm volatile("cp.async.commit_group;\n" ::: "memory");
    };

    const uint32_t a_row  = (uint32_t)(wm * 64 + (lane & 15));
    const uint32_t a_kh   = (uint32_t)((lane >> 4) * 16);
    const uint32_t b_row  = (uint32_t)(wn * 64 + ((lane >> 4) << 3) + (lane & 7));
    const uint32_t b_kh   = (uint32_t)(((lane >> 3) & 1) * 16);

    const int KT = K2 / BK;    // 9

    #pragma unroll
    for (int kt = 0; kt < STAGES - 1; kt++) {
        if (kt < KT) fill(kt);
        else asm volatile("cp.async.commit_group;\n" ::: "memory");
    }

    for (int kt = 0; kt < KT; kt++) {
        asm volatile("cp.async.wait_group %0;\n" :: "n"(STAGES - 2) : "memory");
        __syncthreads();

        if (kt + STAGES - 1 < KT) fill(kt + STAGES - 1);
        else asm volatile("cp.async.commit_group;\n" ::: "memory");

        const int st = kt % STAGES;
        const uint32_t da = saA + st * STAGE_BYTES;
        const uint32_t db = saB + st * STAGE_BYTES;
        #pragma unroll
        for (int k16 = 0; k16 < BK / 16; k16++) {
            uint32_t af[4][4], bf[4][4];
            #pragma unroll
            for (int mt = 0; mt < 4; mt++) {
                uint32_t off = (a_row + mt * 16) * 128 + a_kh + k16 * 32;
                ldm_x4(af[mt], da + sw128(off));
            }
            #pragma unroll
            for (int np = 0; np < 4; np++) {
                uint32_t off = (b_row + np * 16) * 128 + b_kh + k16 * 32;
                ldm_x4(bf[np], db + sw128(off));
            }
            #pragma unroll
            for (int mt = 0; mt < 4; mt++)
                #pragma unroll
                for (int nt = 0; nt < 8; nt++)
                    mma16816(acc[mt][nt], af[mt], &bf[nt >> 1][(nt & 1) * 2]);
        }
    }

    const int er = lane >> 2, ec = (lane & 3) * 2;
    #pragma unroll
    for (int mt = 0; mt < 4; mt++) {
        #pragma unroll
        for (int nt = 0; nt < 8; nt++) {
            int row = m0 + wm * 64 + mt * 16 + er;
            int col = n0 + wn * 64 + nt * 8 + ec;
            float b0 = bias[col], b1 = bias[col + 1];
            float2 v0 = { acc[mt][nt][0] + b0, acc[mt][nt][1] + b1 };
            float2 v1 = { acc[mt][nt][2] + b0, acc[mt][nt][3] + b1 };
            *(float2*)(C + (size_t)row * 512 + col)       = v0;
            *(float2*)(C + (size_t)(row + 8) * 512 + col) = v1;
        }
    }
}

// ---------------- per-row attention (block = row, warp = head) -----------------
__global__ __launch_bounds__(256)
void attn_kernel(const int* __restrict__ col_index, const int* __restrict__ to_col,
                 const float* __restrict__ att_bias, const float* __restrict__ dist,
                 const float* __restrict__ pos, const float* __restrict__ col_pos)
{
    __shared__ int   s_cn[DEG];
    __shared__ float s_cp[DEG][3];
    __shared__ float s_rel[DEG][3];
    __shared__ float s_de[DEG];
    __shared__ float s_att[H_HEADS][DEG];

    int row = blockIdx.x;
    int tid = threadIdx.x;

    if (tid < DEG) {
        int is64 = g_idx64;
        int e  = row * DEG + tid;
        int c  = ldidx(col_index, e, is64);
        int cn = ldidx(to_col,   c, is64);
        s_cn[tid] = cn;
        float px = pos[row*3+0], py = pos[row*3+1], pz = pos[row*3+2];
        float cx = col_pos[c*3+0], cy = col_pos[c*3+1], cz = col_pos[c*3+2];
        s_cp[tid][0]  = cx;      s_cp[tid][1]  = cy;      s_cp[tid][2]  = cz;
        s_rel[tid][0] = cx - px; s_rel[tid][1] = cy - py; s_rel[tid][2] = cz - pz;
        float d0 = dist[e];
        s_de[tid] = (d0 == 0.f) ? INFINITY : d0;
    }
    __syncthreads();

    int h = tid >> 5, lane = tid & 31;
    __half* a2row = g_A2 + (size_t)row * K2;

    const float4* q4 = (const float4*)(g_QK + (size_t)row * QK_LD + h * DKV);
    float4 qf = q4[lane & 15];
    const float* qvp = g_QV + (size_t)row * 128 + h * 3;
    float a0 = qvp[0], a1 = qvp[1], a2 = qvp[2];

    // logits: half-warp per edge, 2 edges per iteration, float4 dot products
    float mylogit = -INFINITY;
    #pragma unroll
    for (int i = 0; i < 8; i++) {
        int j = 2 * i + (lane >> 4);
        const float4* kp4 = (const float4*)(g_QK + (size_t)s_cn[j] * QK_LD + 512 + h * DKV);
        float4 kf = kp4[lane & 15];
        float p = qf.x*kf.x + qf.y*kf.y + qf.z*kf.z + qf.w*kf.w;
        #pragma unroll
        for (int o = 8; o; o >>= 1) p += __shfl_xor_sync(0xffffffffu, p, o);
        float tmp = __shfl_sync(0xffffffffu, p, (lane & 1) << 4);
        if ((lane >> 1) == i) mylogit = tmp;
    }
    if (lane < DEG) {
        float ang = a0*s_rel[lane][0] + a1*s_rel[lane][1] + a2*s_rel[lane][2];
        mylogit += att_bias[(size_t)h * E_EDGES + row * DEG + lane] + ang / s_de[lane];
    }

    // softmax over lanes 0..15
    float m = mylogit;
    #pragma unroll
    for (int o = 16; o; o >>= 1) m = fmaxf(m, __shfl_xor_sync(0xffffffffu, m, o));
    float pe = (lane < DEG) ? expf(mylogit - m) : 0.f;
    float ss = pe;
    #pragma unroll
    for (int o = 16; o; o >>= 1) ss += __shfl_xor_sync(0xffffffffu, ss, o);
    float att  = pe / ss;
    float natt = (lane < DEG) ? att / s_de[lane] : 0.f;
    if (lane < DEG) s_att[h][lane] = att;

    float d0v = (lane < DEG) ? natt * s_cp[lane][0] : 0.f;
    float d1v = (lane < DEG) ? natt * s_cp[lane][1] : 0.f;
    float d2v = (lane < DEG) ? natt * s_cp[lane][2] : 0.f;
    float avg = natt;
    #pragma unroll
    for (int o = 16; o; o >>= 1) {
        d0v += __shfl_xor_sync(0xffffffffu, d0v, o);
        d1v += __shfl_xor_sync(0xffffffffu, d1v, o);
        d2v += __shfl_xor_sync(0xffffffffu, d2v, o);
        avg += __shfl_xor_sync(0xffffffffu, avg, o);
    }
    int kb = h * (DKV + 4);
    if (lane == 0) {
        float px = pos[row*3+0], py = pos[row*3+1], pz = pos[row*3+2];
        float dx = d0v - avg*px, dy = d1v - avg*py, dz = d2v - avg*pz;
        float nrm = sqrtf(dx*dx + dy*dy + dz*dz);
        float inv = 1.f / fmaxf(nrm, 1e-12f);
        *(__half2*)(a2row + kb + DKV + 0) = __floats2half2_rn(dx*inv, dy*inv);
        *(__half2*)(a2row + kb + DKV + 2) = __floats2half2_rn(dz*inv, avg);
    }
    __syncwarp();

    // y = att @ V (fp16 gather), float2 per lane (dims 2*lane, 2*lane+1)
    float2 acc2 = {0.f, 0.f};
    #pragma unroll
    for (int j = 0; j < DEG; j++) {
        const __half2* vp2 = (const __half2*)(g_V + (size_t)s_cn[j] * 512 + h * DKV);
        float2 v = __half22float2(vp2[lane]);
        float a = s_att[h][j];
        acc2.x += a * v.x;
        acc2.y += a * v.y;
    }
    *(__half2*)(a2row + kb + 2 * lane) = __floats2half2_rn(acc2.x, acc2.y);
}

// ---------------- launch --------------------------------------------------------
extern "C" void kernel_launch(void* const* d_in, const int* in_sizes, int n_in,
                              void* d_out, int out_size)
{
    const float* x         = (const float*)d_in[0];
    const int*   col_index = (const int*)  d_in[2];
    const int*   to_col    = (const int*)  d_in[3];
    const float* att_bias  = (const float*)d_in[4];
    const float* dist      = (const float*)d_in[5];
    const float* pos       = (const float*)d_in[6];
    const float* col_pos   = (const float*)d_in[7];
    const float* Wq        = (const float*)d_in[8];
    const float* Wqv       = (const float*)d_in[9];
    const float* Wk        = (const float*)d_in[10];
    const float* Wv        = (const float*)d_in[11];
    const float* Wout      = (const float*)d_in[12];
    const float* bout      = (const float*)d_in[13];
    float*       out       = (float*)d_out;

    void *pA1, *pB1, *pBv, *pA2, *pB2;
    cudaGetSymbolAddress(&pA1, g_A1);
    cudaGetSymbolAddress(&pB1, g_B1);
    cudaGetSymbolAddress(&pBv, g_Bv);
    cudaGetSymbolAddress(&pA2, g_A2);
    cudaGetSymbolAddress(&pB2, g_B2);

    const int SMEM = STAGES * 2 * STAGE_BYTES;     // 98304
    cudaFuncSetAttribute(gemm_proj, cudaFuncAttributeMaxDynamicSharedMemorySize, SMEM);
    cudaFuncSetAttribute(gemm_out,  cudaFuncAttributeMaxDynamicSharedMemorySize, SMEM);

    conv_all<<<CONV_BLOCKS, 256>>>(x, Wq, Wk, Wv, Wqv, Wout, col_index);

    dim3 g1(13, N_NODES / 128);                // 8 qk tiles + 5 v/qv tiles
    gemm_proj<<<g1, 128, SMEM>>>((const __half*)pA1, (const __half*)pB1,
                                 (const __half*)pBv);

    attn_kernel<<<N_NODES, 256>>>(col_index, to_col, att_bias, dist, pos, col_pos);

    dim3 g2(512 / 128, N_NODES / 128);         // 4 x 64
    gemm_out<<<g2, 128, SMEM>>>((const __half*)pA2, (const __half*)pB2, out, bout);
}

// round 13
// speedup vs baseline: 1.2402x; 1.0004x over previous
#include <cuda_runtime.h>
#include <cuda_fp16.h>
#include <math.h>
#include <stdint.h>

#define N_NODES 8192
#define D_DIM   512
#define H_HEADS 8
#define DKV     64
#define DEG     16
#define E_EDGES (N_NODES*DEG)          // 131072
#define FEAT_COLS 544

// GEMM geometry
#define K_QK 1024          // q,k proj: split-fp16 x, K=2*512
#define K_V  512           // v,qv proj: x_hi only
#define K2 576             // out: 544 + 32 zero pad (single-fp16 feat)
#define STAGES 3
#define BK 64
#define STAGE_BYTES (128 * BK * 2)     // 16384 per operand per stage

// ---------------- device-global scratch (no allocations allowed) ------------
__device__ __half g_A1[(size_t)N_NODES * K_QK];   // [x_hi | x_lo]
__device__ __half g_B1[(size_t)1024 * K_QK];      // q,k weights: [W_hi | W_hi]
__device__ __half g_Bv[(size_t)640 * K_V];        // v (0-511), qv (512-535), zero pad
__device__ float  g_Q [(size_t)N_NODES * 512];    // q fp32
__device__ __half g_K [(size_t)N_NODES * 512];    // k fp16 (gathered operand)
__device__ float  g_QV[(size_t)N_NODES * 128];    // qv (cols 0-23 used)
__device__ __half g_V [(size_t)N_NODES * 512];    // v in fp16
__device__ __half g_A2[(size_t)N_NODES * K2];     // feat fp16 (cols 544.. stay 0)
__device__ __half g_B2[(size_t)512 * K2];         // Wout fp16 (cols 544.. stay 0)
__device__ int    g_idx64;

// ---------------- helpers -----------------------------------------------------
__device__ __forceinline__ uint32_t smem_u32(const void* p) {
    uint32_t a;
    asm("{ .reg .u64 t; cvta.to.shared.u64 t, %1; cvt.u32.u64 %0, t; }" : "=r"(a) : "l"(p));
    return a;
}
__device__ __forceinline__ void cp_async16(uint32_t saddr, const void* g) {
    asm volatile("cp.async.cg.shared.global [%0], [%1], 16;\n" :: "r"(saddr), "l"(g));
}
__device__ __forceinline__ void ldm_x4(uint32_t* r, uint32_t addr) {
    asm volatile("ldmatrix.sync.aligned.m8n8.x4.shared.b16 {%0,%1,%2,%3}, [%4];"
                 : "=r"(r[0]), "=r"(r[1]), "=r"(r[2]), "=r"(r[3]) : "r"(addr));
}
__device__ __forceinline__ void mma16816(float* d, const uint32_t* a, const uint32_t* b) {
    asm volatile("mma.sync.aligned.m16n8k16.row.col.f32.f16.f16.f32 "
                 "{%0,%1,%2,%3}, {%4,%5,%6,%7}, {%8,%9}, {%0,%1,%2,%3};"
                 : "+f"(d[0]), "+f"(d[1]), "+f"(d[2]), "+f"(d[3])
                 : "r"(a[0]), "r"(a[1]), "r"(a[2]), "r"(a[3]), "r"(b[0]), "r"(b[1]));
}
__device__ __forceinline__ uint32_t sw128(uint32_t off) {  // 128B-row swizzle
    return off ^ ((off >> 3) & 0x70);
}

__device__ __forceinline__ int ldidx(const int* __restrict__ p, int i, int is64) {
    return is64 ? p[(size_t)2*i] : p[i];
}

// ---------------- split conversions --------------------------------------------
__device__ __forceinline__ void split_f16(float v, __half& hi, __half& lo) {
    hi = __float2half(v);
    lo = __float2half(v - __half2float(hi));
}

// ---------------- merged conversion kernel (one launch) ------------------------
#define CX_BLOCKS 16384
#define CW_BLOCKS 3328
#define CO_BLOCKS 1088
#define CONV_BLOCKS (CX_BLOCKS + CW_BLOCKS + CO_BLOCKS)

__global__ __launch_bounds__(256) void conv_all(
        const float* __restrict__ x,
        const float* __restrict__ Wq, const float* __restrict__ Wk,
        const float* __restrict__ Wv, const float* __restrict__ Wqv,
        const float* __restrict__ Wout, const int* __restrict__ ci)
{
    int b = blockIdx.x;
    if (b < CX_BLOCKS) {
        int idx = b * 256 + threadIdx.x;
        if (idx >= N_NODES * D_DIM) return;
        int m = idx >> 9, k = idx & 511;
        __half hi, lo; split_f16(x[idx], hi, lo);
        __half* r = g_A1 + (size_t)m * K_QK;
        r[k] = hi; r[512 + k] = lo;
    } else if (b < CX_BLOCKS + CW_BLOCKS) {
        if (b == CX_BLOCKS && threadIdx.x == 0) {   // detect index dtype
            int all0 = 1;
            #pragma unroll
            for (int i = 0; i < 64; i++)
                if (ci[2*i + 1] != 0) { all0 = 0; break; }
            g_idx64 = all0;
        }
        int idx = (b - CX_BLOCKS) * 256 + threadIdx.x;
        if (idx >= 1560 * 512) return;
        int n = idx / 512, k = idx % 512;
        if (n < 1024) {                              // q,k -> B1 (split layout)
            float v = (n < 512) ? Wq[n * 512 + k] * 0.125f
                                : Wk[(n - 512) * 512 + k];
            __half hi = __float2half(v);
            __half* r = g_B1 + (size_t)n * K_QK;
            r[k] = hi; r[512 + k] = hi;
        } else {                                     // v, qv -> Bv (single layout)
            int n2 = n - 1024;                       // 0..535
            float v = (n2 < 512) ? Wv[n2 * 512 + k]
                                 : Wqv[(n2 - 512) * 512 + k];
            g_Bv[(size_t)n2 * K_V + k] = __float2half(v);
        }
    } else {
        int idx = (b - CX_BLOCKS - CW_BLOCKS) * 256 + threadIdx.x;
        if (idx >= 512 * 544) return;
        int n = idx / 544, k = idx % 544;
        g_B2[(size_t)n * K2 + k] = __float2half(Wout[(size_t)n * FEAT_COLS + k]);
    }
}

// ---------------- fused projection GEMM ---------------------------------------
// grid = (13, M/128): bx<4 -> q (fp32 g_Q), bx in [4,8) -> k (fp16 g_K),
//                     bx>=8 -> v/qv (K=512; v -> fp16 g_V, qv -> fp32 g_QV)
__global__ __launch_bounds__(128, 2)
void gemm_proj(const __half* __restrict__ A, const __half* __restrict__ B1,
               const __half* __restrict__ Bv)
{
    extern __shared__ __align__(1024) __half smem[];
    __half* sA = smem;
    __half* sB = smem + STAGES * 128 * BK;

    const int tid = threadIdx.x, wid = tid >> 5, lane = tid & 31;
    const bool qk = (blockIdx.x < 8);
    const int m0 = blockIdx.y * 128;
    const int n0 = qk ? blockIdx.x * 128 : (blockIdx.x - 8) * 128;
    const int K  = qk ? K_QK : K_V;
    const __half* B = qk ? B1 : Bv;
    const int wm = wid & 1, wn = wid >> 1;             // warp tile 64(m) x 64(n)

    float acc[4][8][4];
    #pragma unroll
    for (int i = 0; i < 4; i++)
        #pragma unroll
        for (int j = 0; j < 8; j++)
            #pragma unroll
            for (int t = 0; t < 4; t++) acc[i][j][t] = 0.f;

    const uint32_t saA = smem_u32(sA), saB = smem_u32(sB);

    auto fill = [&](int kt) {
        const int st = kt % STAGES;
        const uint32_t da = saA + st * STAGE_BYTES;
        const uint32_t db = saB + st * STAGE_BYTES;
        const int k0 = kt * BK;
        #pragma unroll
        for (int i = 0; i < 8; i++) {
            int idx = tid + i * 128;
            int r = idx >> 3, c = idx & 7;
            uint32_t sw = sw128((uint32_t)(r * 128 + c * 16));
            cp_async16(da + sw, A + (size_t)(m0 + r) * K_QK + k0 + c * 8);
        }
        #pragma unroll
        for (int i = 0; i < 8; i++) {
            int idx = tid + i * 128;
            int r = idx >> 3, c = idx & 7;
            uint32_t sw = sw128((uint32_t)(r * 128 + c * 16));
            cp_async16(db + sw, B + (size_t)(n0 + r) * K + k0 + c * 8);
        }
        asm volatile("cp.async.commit_group;\n" ::: "memory");
    };

    const uint32_t a_row  = (uint32_t)(wm * 64 + (lane & 15));
    const uint32_t a_kh   = (uint32_t)((lane >> 4) * 16);
    const uint32_t b_row  = (uint32_t)(wn * 64 + ((lane >> 4) << 3) + (lane & 7));
    const uint32_t b_kh   = (uint32_t)(((lane >> 3) & 1) * 16);

    const int KT = K / BK;

    #pragma unroll
    for (int kt = 0; kt < STAGES - 1; kt++) {
        if (kt < KT) fill(kt);
        else asm volatile("cp.async.commit_group;\n" ::: "memory");
    }

    for (int kt = 0; kt < KT; kt++) {
        asm volatile("cp.async.wait_group %0;\n" :: "n"(STAGES - 2) : "memory");
        __syncthreads();

        if (kt + STAGES - 1 < KT) fill(kt + STAGES - 1);
        else asm volatile("cp.async.commit_group;\n" ::: "memory");

        const int st = kt % STAGES;
        const uint32_t da = saA + st * STAGE_BYTES;
        const uint32_t db = saB + st * STAGE_BYTES;
        #pragma unroll
        for (int k16 = 0; k16 < BK / 16; k16++) {
            uint32_t af[4][4], bf[4][4];
            #pragma unroll
            for (int mt = 0; mt < 4; mt++) {
                uint32_t off = (a_row + mt * 16) * 128 + a_kh + k16 * 32;
                ldm_x4(af[mt], da + sw128(off));
            }
            #pragma unroll
            for (int np = 0; np < 4; np++) {
                uint32_t off = (b_row + np * 16) * 128 + b_kh + k16 * 32;
                ldm_x4(bf[np], db + sw128(off));
            }
            #pragma unroll
            for (int mt = 0; mt < 4; mt++)
                #pragma unroll
                for (int nt = 0; nt < 8; nt++)
                    mma16816(acc[mt][nt], af[mt], &bf[nt >> 1][(nt & 1) * 2]);
        }
    }

    // epilogue
    const int er = lane >> 2, ec = (lane & 3) * 2;
    if (qk && n0 < 512) {                              // q -> fp32 g_Q
        #pragma unroll
        for (int mt = 0; mt < 4; mt++) {
            #pragma unroll
            for (int nt = 0; nt < 8; nt++) {
                int row = m0 + wm * 64 + mt * 16 + er;
                int col = n0 + wn * 64 + nt * 8 + ec;
                float2 v0 = { acc[mt][nt][0], acc[mt][nt][1] };
                float2 v1 = { acc[mt][nt][2], acc[mt][nt][3] };
                *(float2*)(g_Q + (size_t)row * 512 + col)       = v0;
                *(float2*)(g_Q + (size_t)(row + 8) * 512 + col) = v1;
            }
        }
    } else if (qk) {                                   // k -> fp16 g_K
        #pragma unroll
        for (int mt = 0; mt < 4; mt++) {
            #pragma unroll
            for (int nt = 0; nt < 8; nt++) {
                int row  = m0 + wm * 64 + mt * 16 + er;
                int kcol = n0 - 512 + wn * 64 + nt * 8 + ec;
                __half2 v0 = __floats2half2_rn(acc[mt][nt][0], acc[mt][nt][1]);
                __half2 v1 = __floats2half2_rn(acc[mt][nt][2], acc[mt][nt][3]);
                *(__half2*)(g_K + (size_t)row * 512 + kcol)       = v0;
                *(__half2*)(g_K + (size_t)(row + 8) * 512 + kcol) = v1;
            }
        }
    } else if (n0 < 512) {                             // v -> fp16 g_V
        #pragma unroll
        for (int mt = 0; mt < 4; mt++) {
            #pragma unroll
            for (int nt = 0; nt < 8; nt++) {
                int row  = m0 + wm * 64 + mt * 16 + er;
                int vcol = n0 + wn * 64 + nt * 8 + ec;
                __half2 v0 = __floats2half2_rn(acc[mt][nt][0], acc[mt][nt][1]);
                __half2 v1 = __floats2half2_rn(acc[mt][nt][2], acc[mt][nt][3]);
                *(__half2*)(g_V + (size_t)row * 512 + vcol)       = v0;
                *(__half2*)(g_V + (size_t)(row + 8) * 512 + vcol) = v1;
            }
        }
    } else {                                           // qv -> fp32 g_QV (128 cols)
        #pragma unroll
        for (int mt = 0; mt < 4; mt++) {
            #pragma unroll
            for (int nt = 0; nt < 8; nt++) {
                int row = m0 + wm * 64 + mt * 16 + er;
                int col = wn * 64 + nt * 8 + ec;       // n0==512 -> local col
                float2 v0 = { acc[mt][nt][0], acc[mt][nt][1] };
                float2 v1 = { acc[mt][nt][2], acc[mt][nt][3] };
                *(float2*)(g_QV + (size_t)row * 128 + col)       = v0;
                *(float2*)(g_QV + (size_t)(row + 8) * 128 + col) = v1;
            }
        }
    }
}

// ---------------- output GEMM: out = A2 @ B2^T + bout --------------------------
__global__ __launch_bounds__(128, 2)
void gemm_out(const __half* __restrict__ A, const __half* __restrict__ B,
              float* __restrict__ C, const float* __restrict__ bias)
{
    extern __shared__ __align__(1024) __half smem[];
    __half* sA = smem;
    __half* sB = smem + STAGES * 128 * BK;

    const int tid = threadIdx.x, wid = tid >> 5, lane = tid & 31;
    const int m0 = blockIdx.y * 128, n0 = blockIdx.x * 128;
    const int wm = wid & 1, wn = wid >> 1;

    float acc[4][8][4];
    #pragma unroll
    for (int i = 0; i < 4; i++)
        #pragma unroll
        for (int j = 0; j < 8; j++)
            #pragma unroll
            for (int t = 0; t < 4; t++) acc[i][j][t] = 0.f;

    const uint32_t saA = smem_u32(sA), saB = smem_u32(sB);

    auto fill = [&](int kt) {
        const int st = kt % STAGES;
        const uint32_t da = saA + st * STAGE_BYTES;
        const uint32_t db = saB + st * STAGE_BYTES;
        const int k0 = kt * BK;
        #pragma unroll
        for (int i = 0; i < 8; i++) {
            int idx = tid + i * 128;
            int r = idx >> 3, c = idx & 7;
            uint32_t sw = sw128((uint32_t)(r * 128 + c * 16));
            cp_async16(da + sw, A + (size_t)(m0 + r) * K2 + k0 + c * 8);
        }
        #pragma unroll
        for (int i = 0; i < 8; i++) {
            int idx = tid + i * 128;
            int r = idx >> 3, c = idx & 7;
            uint32_t sw = sw128((uint32_t)(r * 128 + c * 16));
            cp_async16(db + sw, B + (size_t)(n0 + r) * K2 + k0 + c * 8);
        }
        asm volatile("cp.async.commit_group;\n" ::: "memory");
    };

    const uint32_t a_row  = (uint32_t)(wm * 64 + (lane & 15));
    const uint32_t a_kh   = (uint32_t)((lane >> 4) * 16);
    const uint32_t b_row  = (uint32_t)(wn * 64 + ((lane >> 4) << 3) + (lane & 7));
    const uint32_t b_kh   = (uint32_t)(((lane >> 3) & 1) * 16);

    const int KT = K2 / BK;    // 9

    #pragma unroll
    for (int kt = 0; kt < STAGES - 1; kt++) {
        if (kt < KT) fill(kt);
        else asm volatile("cp.async.commit_group;\n" ::: "memory");
    }

    for (int kt = 0; kt < KT; kt++) {
        asm volatile("cp.async.wait_group %0;\n" :: "n"(STAGES - 2) : "memory");
        __syncthreads();

        if (kt + STAGES - 1 < KT) fill(kt + STAGES - 1);
        else asm volatile("cp.async.commit_group;\n" ::: "memory");

        const int st = kt % STAGES;
        const uint32_t da = saA + st * STAGE_BYTES;
        const uint32_t db = saB + st * STAGE_BYTES;
        #pragma unroll
        for (int k16 = 0; k16 < BK / 16; k16++) {
            uint32_t af[4][4], bf[4][4];
            #pragma unroll
            for (int mt = 0; mt < 4; mt++) {
                uint32_t off = (a_row + mt * 16) * 128 + a_kh + k16 * 32;
                ldm_x4(af[mt], da + sw128(off));
            }
            #pragma unroll
            for (int np = 0; np < 4; np++) {
                uint32_t off = (b_row + np * 16) * 128 + b_kh + k16 * 32;
                ldm_x4(bf[np], db + sw128(off));
            }
            #pragma unroll
            for (int mt = 0; mt < 4; mt++)
                #pragma unroll
                for (int nt = 0; nt < 8; nt++)
                    mma16816(acc[mt][nt], af[mt], &bf[nt >> 1][(nt & 1) * 2]);
        }
    }

    const int er = lane >> 2, ec = (lane & 3) * 2;
    #pragma unroll
    for (int mt = 0; mt < 4; mt++) {
        #pragma unroll
        for (int nt = 0; nt < 8; nt++) {
            int row = m0 + wm * 64 + mt * 16 + er;
            int col = n0 + wn * 64 + nt * 8 + ec;
            float b0 = bias[col], b1 = bias[col + 1];
            float2 v0 = { acc[mt][nt][0] + b0, acc[mt][nt][1] + b1 };
            float2 v1 = { acc[mt][nt][2] + b0, acc[mt][nt][3] + b1 };
            *(float2*)(C + (size_t)row * 512 + col)       = v0;
            *(float2*)(C + (size_t)(row + 8) * 512 + col) = v1;
        }
    }
}

// ---------------- per-row attention (block = row, warp = head) -----------------
__global__ __launch_bounds__(256)
void attn_kernel(const int* __restrict__ col_index, const int* __restrict__ to_col,
                 const float* __restrict__ att_bias, const float* __restrict__ dist,
                 const float* __restrict__ pos, const float* __restrict__ col_pos)
{
    __shared__ int   s_cn[DEG];
    __shared__ float s_cp[DEG][3];
    __shared__ float s_rel[DEG][3];
    __shared__ float s_de[DEG];
    __shared__ float s_att[H_HEADS][DEG];

    int row = blockIdx.x;
    int tid = threadIdx.x;

    if (tid < DEG) {
        int is64 = g_idx64;
        int e  = row * DEG + tid;
        int c  = ldidx(col_index, e, is64);
        int cn = ldidx(to_col,   c, is64);
        s_cn[tid] = cn;
        float px = pos[row*3+0], py = pos[row*3+1], pz = pos[row*3+2];
        float cx = col_pos[c*3+0], cy = col_pos[c*3+1], cz = col_pos[c*3+2];
        s_cp[tid][0]  = cx;      s_cp[tid][1]  = cy;      s_cp[tid][2]  = cz;
        s_rel[tid][0] = cx - px; s_rel[tid][1] = cy - py; s_rel[tid][2] = cz - pz;
        float d0 = dist[e];
        s_de[tid] = (d0 == 0.f) ? INFINITY : d0;
    }
    __syncthreads();

    int h = tid >> 5, lane = tid & 31;
    __half* a2row = g_A2 + (size_t)row * K2;

    const float4* q4 = (const float4*)(g_Q + (size_t)row * 512 + h * DKV);
    float4 qf = q4[lane & 15];
    const float* qvp = g_QV + (size_t)row * 128 + h * 3;
    float a0 = qvp[0], a1 = qvp[1], a2 = qvp[2];

    // logits: half-warp per edge, 2 edges per iteration, fp16 k gathers
    float mylogit = -INFINITY;
    #pragma unroll
    for (int i = 0; i < 8; i++) {
        int j = 2 * i + (lane >> 4);
        const uint2* kp = (const uint2*)(g_K + (size_t)s_cn[j] * 512 + h * DKV);
        uint2 kraw = kp[lane & 15];
        float2 f01 = __half22float2(*(__half2*)&kraw.x);
        float2 f23 = __half22float2(*(__half2*)&kraw.y);
        float p = qf.x*f01.x + qf.y*f01.y + qf.z*f23.x + qf.w*f23.y;
        #pragma unroll
        for (int o = 8; o; o >>= 1) p += __shfl_xor_sync(0xffffffffu, p, o);
        float tmp = __shfl_sync(0xffffffffu, p, (lane & 1) << 4);
        if ((lane >> 1) == i) mylogit = tmp;
    }
    if (lane < DEG) {
        float ang = a0*s_rel[lane][0] + a1*s_rel[lane][1] + a2*s_rel[lane][2];
        mylogit += att_bias[(size_t)h * E_EDGES + row * DEG + lane] + ang / s_de[lane];
    }

    // softmax over lanes 0..15
    float m = mylogit;
    #pragma unroll
    for (int o = 16; o; o >>= 1) m = fmaxf(m, __shfl_xor_sync(0xffffffffu, m, o));
    float pe = (lane < DEG) ? expf(mylogit - m) : 0.f;
    float ss = pe;
    #pragma unroll
    for (int o = 16; o; o >>= 1) ss += __shfl_xor_sync(0xffffffffu, ss, o);
    float att  = pe / ss;
    float natt = (lane < DEG) ? att / s_de[lane] : 0.f;
    if (lane < DEG) s_att[h][lane] = att;

    float d0v = (lane < DEG) ? natt * s_cp[lane][0] : 0.f;
    float d1v = (lane < DEG) ? natt * s_cp[lane][1] : 0.f;
    float d2v = (lane < DEG) ? natt * s_cp[lane][2] : 0.f;
    float avg = natt;
    #pragma unroll
    for (int o = 16; o; o >>= 1) {
        d0v += __shfl_xor_sync(0xffffffffu, d0v, o);
        d1v += __shfl_xor_sync(0xffffffffu, d1v, o);
        d2v += __shfl_xor_sync(0xffffffffu, d2v, o);
        avg += __shfl_xor_sync(0xffffffffu, avg, o);
    }
    int kb = h * (DKV + 4);
    if (lane == 0) {
        float px = pos[row*3+0], py = pos[row*3+1], pz = pos[row*3+2];
        float dx = d0v - avg*px, dy = d1v - avg*py, dz = d2v - avg*pz;
        float nrm = sqrtf(dx*dx + dy*dy + dz*dz);
        float inv = 1.f / fmaxf(nrm, 1e-12f);
        *(__half2*)(a2row + kb + DKV + 0) = __floats2half2_rn(dx*inv, dy*inv);
        *(__half2*)(a2row + kb + DKV + 2) = __floats2half2_rn(dz*inv, avg);
    }
    __syncwarp();

    // y = att @ V (fp16 gather), float2 per lane (dims 2*lane, 2*lane+1)
    float2 acc2 = {0.f, 0.f};
    #pragma unroll
    for (int j = 0; j < DEG; j++) {
        const __half2* vp2 = (const __half2*)(g_V + (size_t)s_cn[j] * 512 + h * DKV);
        float2 v = __half22float2(vp2[lane]);
        float a = s_att[h][j];
        acc2.x += a * v.x;
        acc2.y += a * v.y;
    }
    *(__half2*)(a2row + kb + 2 * lane) = __floats2half2_rn(acc2.x, acc2.y);
}

// ---------------- launch --------------------------------------------------------
extern "C" void kernel_launch(void* const* d_in, const int* in_sizes, int n_in,
                              void* d_out, int out_size)
{
    const float* x         = (const float*)d_in[0];
    const int*   col_index = (const int*)  d_in[2];
    const int*   to_col    = (const int*)  d_in[3];
    const float* att_bias  = (const float*)d_in[4];
    const float* dist      = (const float*)d_in[5];
    const float* pos       = (const float*)d_in[6];
    const float* col_pos   = (const float*)d_in[7];
    const float* Wq        = (const float*)d_in[8];
    const float* Wqv       = (const float*)d_in[9];
    const float* Wk        = (const float*)d_in[10];
    const float* Wv        = (const float*)d_in[11];
    const float* Wout      = (const float*)d_in[12];
    const float* bout      = (const float*)d_in[13];
    float*       out       = (float*)d_out;

    void *pA1, *pB1, *pBv, *pA2, *pB2;
    cudaGetSymbolAddress(&pA1, g_A1);
    cudaGetSymbolAddress(&pB1, g_B1);
    cudaGetSymbolAddress(&pBv, g_Bv);
    cudaGetSymbolAddress(&pA2, g_A2);
    cudaGetSymbolAddress(&pB2, g_B2);

    const int SMEM = STAGES * 2 * STAGE_BYTES;     // 98304
    cudaFuncSetAttribute(gemm_proj, cudaFuncAttributeMaxDynamicSharedMemorySize, SMEM);
    cudaFuncSetAttribute(gemm_out,  cudaFuncAttributeMaxDynamicSharedMemorySize, SMEM);

    conv_all<<<CONV_BLOCKS, 256>>>(x, Wq, Wk, Wv, Wqv, Wout, col_index);

    dim3 g1(13, N_NODES / 128);                // 4 q + 4 k + 5 v/qv tiles
    gemm_proj<<<g1, 128, SMEM>>>((const __half*)pA1, (const __half*)pB1,
                                 (const __half*)pBv);

    attn_kernel<<<N_NODES, 256>>>(col_index, to_col, att_bias, dist, pos, col_pos);

    dim3 g2(512 / 128, N_NODES / 128);         // 4 x 64
    gemm_out<<<g2, 128, SMEM>>>((const __half*)pA2, (const __half*)pB2, out, bout);
}

// round 14
// speedup vs baseline: 1.5966x; 1.2874x over previous
#include <cuda_runtime.h>
#include <cuda_fp16.h>
#include <math.h>
#include <stdint.h>

#define N_NODES 8192
#define D_DIM   512
#define H_HEADS 8
#define DKV     64
#define DEG     16
#define E_EDGES (N_NODES*DEG)          // 131072
#define FEAT_COLS 544

// GEMM geometry
#define K1 512             // proj: x_hi only, all outputs
#define B1_ROWS 1664       // q(0-511) k(512-1023) v(1024-1535) qv(1536-1559) +pad
#define K2 576             // out: 544 + 32 zero pad (single-fp16 feat)
#define STAGES 3
#define BK 64
#define STAGE_BYTES (128 * BK * 2)     // 16384 per operand per stage

// ---------------- device-global scratch (no allocations allowed) ------------
__device__ __half g_A1[(size_t)N_NODES * K1];     // x_hi
__device__ __half g_B1[(size_t)B1_ROWS * K1];     // all proj weights (pad rows 0)
__device__ float  g_Q [(size_t)N_NODES * 512];    // q fp32
__device__ __half g_K [(size_t)N_NODES * 512];    // k fp16 (gathered operand)
__device__ float  g_QV[(size_t)N_NODES * 128];    // qv (cols 0-23 used)
__device__ __half g_V [(size_t)N_NODES * 512];    // v fp16
__device__ __half g_A2[(size_t)N_NODES * K2];     // feat fp16 (cols 544.. stay 0)
__device__ __half g_B2[(size_t)512 * K2];         // Wout fp16 (cols 544.. stay 0)
__device__ int    g_idx64;

// ---------------- helpers -----------------------------------------------------
__device__ __forceinline__ uint32_t smem_u32(const void* p) {
    uint32_t a;
    asm("{ .reg .u64 t; cvta.to.shared.u64 t, %1; cvt.u32.u64 %0, t; }" : "=r"(a) : "l"(p));
    return a;
}
__device__ __forceinline__ void cp_async16(uint32_t saddr, const void* g) {
    asm volatile("cp.async.cg.shared.global [%0], [%1], 16;\n" :: "r"(saddr), "l"(g));
}
__device__ __forceinline__ void ldm_x4(uint32_t* r, uint32_t addr) {
    asm volatile("ldmatrix.sync.aligned.m8n8.x4.shared.b16 {%0,%1,%2,%3}, [%4];"
                 : "=r"(r[0]), "=r"(r[1]), "=r"(r[2]), "=r"(r[3]) : "r"(addr));
}
__device__ __forceinline__ void mma16816(float* d, const uint32_t* a, const uint32_t* b) {
    asm volatile("mma.sync.aligned.m16n8k16.row.col.f32.f16.f16.f32 "
                 "{%0,%1,%2,%3}, {%4,%5,%6,%7}, {%8,%9}, {%0,%1,%2,%3};"
                 : "+f"(d[0]), "+f"(d[1]), "+f"(d[2]), "+f"(d[3])
                 : "r"(a[0]), "r"(a[1]), "r"(a[2]), "r"(a[3]), "r"(b[0]), "r"(b[1]));
}
__device__ __forceinline__ uint32_t sw128(uint32_t off) {  // 128B-row swizzle
    return off ^ ((off >> 3) & 0x70);
}

__device__ __forceinline__ int ldidx(const int* __restrict__ p, int i, int is64) {
    return is64 ? p[(size_t)2*i] : p[i];
}

// ---------------- merged conversion kernel (one launch) ------------------------
#define CX_BLOCKS 8192     // x -> x_hi, 2 floats/thread
#define CW_BLOCKS 3120     // 1560*512 weights
#define CO_BLOCKS 1088     // Wout
#define CONV_BLOCKS (CX_BLOCKS + CW_BLOCKS + CO_BLOCKS)

__global__ __launch_bounds__(256) void conv_all(
        const float* __restrict__ x,
        const float* __restrict__ Wq, const float* __restrict__ Wk,
        const float* __restrict__ Wv, const float* __restrict__ Wqv,
        const float* __restrict__ Wout, const int* __restrict__ ci)
{
    int b = blockIdx.x;
    if (b < CX_BLOCKS) {
        int e2 = b * 256 + threadIdx.x;                // half2 index
        if (e2 >= N_NODES * (K1 / 2)) return;
        float2 v = *(const float2*)(x + (size_t)e2 * 2);
        *(__half2*)(g_A1 + (size_t)e2 * 2) = __floats2half2_rn(v.x, v.y);
    } else if (b < CX_BLOCKS + CW_BLOCKS) {
        if (b == CX_BLOCKS && threadIdx.x == 0) {      // detect index dtype
            int all0 = 1;
            #pragma unroll
            for (int i = 0; i < 64; i++)
                if (ci[2*i + 1] != 0) { all0 = 0; break; }
            g_idx64 = all0;
        }
        int idx = (b - CX_BLOCKS) * 256 + threadIdx.x;
        if (idx >= 1560 * 512) return;
        int n = idx / 512, k = idx % 512;
        float v;
        if      (n < 512)  v = Wq[n * 512 + k] * 0.125f;   // fold 1/sqrt(dk)
        else if (n < 1024) v = Wk[(n - 512) * 512 + k];
        else if (n < 1536) v = Wv[(n - 1024) * 512 + k];
        else               v = Wqv[(n - 1536) * 512 + k];
        g_B1[(size_t)n * K1 + k] = __float2half(v);
    } else {
        int idx = (b - CX_BLOCKS - CW_BLOCKS) * 256 + threadIdx.x;
        if (idx >= 512 * 544) return;
        int n = idx / 544, k = idx % 544;
        g_B2[(size_t)n * K2 + k] = __float2half(Wout[(size_t)n * FEAT_COLS + k]);
    }
}

// ---------------- fused projection GEMM (uniform K=512) ------------------------
// grid = (13, M/128). Column tiles: 0-3 q | 4-7 k | 8-11 v | 12 qv.
__global__ __launch_bounds__(128, 2)
void gemm_proj(const __half* __restrict__ A, const __half* __restrict__ B)
{
    extern __shared__ __align__(1024) __half smem[];
    __half* sA = smem;
    __half* sB = smem + STAGES * 128 * BK;

    const int tid = threadIdx.x, wid = tid >> 5, lane = tid & 31;
    const int m0 = blockIdx.y * 128, n0 = blockIdx.x * 128;
    const int wm = wid & 1, wn = wid >> 1;             // warp tile 64(m) x 64(n)

    float acc[4][8][4];
    #pragma unroll
    for (int i = 0; i < 4; i++)
        #pragma unroll
        for (int j = 0; j < 8; j++)
            #pragma unroll
            for (int t = 0; t < 4; t++) acc[i][j][t] = 0.f;

    const uint32_t saA = smem_u32(sA), saB = smem_u32(sB);

    auto fill = [&](int kt) {
        const int st = kt % STAGES;
        const uint32_t da = saA + st * STAGE_BYTES;
        const uint32_t db = saB + st * STAGE_BYTES;
        const int k0 = kt * BK;
        #pragma unroll
        for (int i = 0; i < 8; i++) {
            int idx = tid + i * 128;
            int r = idx >> 3, c = idx & 7;
            uint32_t sw = sw128((uint32_t)(r * 128 + c * 16));
            cp_async16(da + sw, A + (size_t)(m0 + r) * K1 + k0 + c * 8);
        }
        #pragma unroll
        for (int i = 0; i < 8; i++) {
            int idx = tid + i * 128;
            int r = idx >> 3, c = idx & 7;
            uint32_t sw = sw128((uint32_t)(r * 128 + c * 16));
            cp_async16(db + sw, B + (size_t)(n0 + r) * K1 + k0 + c * 8);
        }
        asm volatile("cp.async.commit_group;\n" ::: "memory");
    };

    const uint32_t a_row  = (uint32_t)(wm * 64 + (lane & 15));
    const uint32_t a_kh   = (uint32_t)((lane >> 4) * 16);
    const uint32_t b_row  = (uint32_t)(wn * 64 + ((lane >> 4) << 3) + (lane & 7));
    const uint32_t b_kh   = (uint32_t)(((lane >> 3) & 1) * 16);

    const int KT = K1 / BK;    // 8

    #pragma unroll
    for (int kt = 0; kt < STAGES - 1; kt++) fill(kt);

    for (int kt = 0; kt < KT; kt++) {
        asm volatile("cp.async.wait_group %0;\n" :: "n"(STAGES - 2) : "memory");
        __syncthreads();

        if (kt + STAGES - 1 < KT) fill(kt + STAGES - 1);
        else asm volatile("cp.async.commit_group;\n" ::: "memory");

        const int st = kt % STAGES;
        const uint32_t da = saA + st * STAGE_BYTES;
        const uint32_t db = saB + st * STAGE_BYTES;
        #pragma unroll
        for (int k16 = 0; k16 < BK / 16; k16++) {
            uint32_t af[4][4], bf[4][4];
            #pragma unroll
            for (int mt = 0; mt < 4; mt++) {
                uint32_t off = (a_row + mt * 16) * 128 + a_kh + k16 * 32;
                ldm_x4(af[mt], da + sw128(off));
            }
            #pragma unroll
            for (int np = 0; np < 4; np++) {
                uint32_t off = (b_row + np * 16) * 128 + b_kh + k16 * 32;
                ldm_x4(bf[np], db + sw128(off));
            }
            #pragma unroll
            for (int mt = 0; mt < 4; mt++)
                #pragma unroll
                for (int nt = 0; nt < 8; nt++)
                    mma16816(acc[mt][nt], af[mt], &bf[nt >> 1][(nt & 1) * 2]);
        }
    }

    // epilogue: route by column tile
    const int er = lane >> 2, ec = (lane & 3) * 2;
    if (n0 < 512) {                                    // q -> fp32 g_Q
        #pragma unroll
        for (int mt = 0; mt < 4; mt++) {
            #pragma unroll
            for (int nt = 0; nt < 8; nt++) {
                int row = m0 + wm * 64 + mt * 16 + er;
                int col = n0 + wn * 64 + nt * 8 + ec;
                float2 v0 = { acc[mt][nt][0], acc[mt][nt][1] };
                float2 v1 = { acc[mt][nt][2], acc[mt][nt][3] };
                *(float2*)(g_Q + (size_t)row * 512 + col)       = v0;
                *(float2*)(g_Q + (size_t)(row + 8) * 512 + col) = v1;
            }
        }
    } else if (n0 < 1024) {                            // k -> fp16 g_K
        #pragma unroll
        for (int mt = 0; mt < 4; mt++) {
            #pragma unroll
            for (int nt = 0; nt < 8; nt++) {
                int row  = m0 + wm * 64 + mt * 16 + er;
                int kcol = n0 - 512 + wn * 64 + nt * 8 + ec;
                __half2 v0 = __floats2half2_rn(acc[mt][nt][0], acc[mt][nt][1]);
                __half2 v1 = __floats2half2_rn(acc[mt][nt][2], acc[mt][nt][3]);
                *(__half2*)(g_K + (size_t)row * 512 + kcol)       = v0;
                *(__half2*)(g_K + (size_t)(row + 8) * 512 + kcol) = v1;
            }
        }
    } else if (n0 < 1536) {                            // v -> fp16 g_V
        #pragma unroll
        for (int mt = 0; mt < 4; mt++) {
            #pragma unroll
            for (int nt = 0; nt < 8; nt++) {
                int row  = m0 + wm * 64 + mt * 16 + er;
                int vcol = n0 - 1024 + wn * 64 + nt * 8 + ec;
                __half2 v0 = __floats2half2_rn(acc[mt][nt][0], acc[mt][nt][1]);
                __half2 v1 = __floats2half2_rn(acc[mt][nt][2], acc[mt][nt][3]);
                *(__half2*)(g_V + (size_t)row * 512 + vcol)       = v0;
                *(__half2*)(g_V + (size_t)(row + 8) * 512 + vcol) = v1;
            }
        }
    } else {                                           // qv -> fp32 g_QV (128 cols)
        #pragma unroll
        for (int mt = 0; mt < 4; mt++) {
            #pragma unroll
            for (int nt = 0; nt < 8; nt++) {
                int row = m0 + wm * 64 + mt * 16 + er;
                int col = wn * 64 + nt * 8 + ec;
                float2 v0 = { acc[mt][nt][0], acc[mt][nt][1] };
                float2 v1 = { acc[mt][nt][2], acc[mt][nt][3] };
                *(float2*)(g_QV + (size_t)row * 128 + col)       = v0;
                *(float2*)(g_QV + (size_t)(row + 8) * 128 + col) = v1;
            }
        }
    }
}

// ---------------- output GEMM: out = A2 @ B2^T + bout --------------------------
__global__ __launch_bounds__(128, 2)
void gemm_out(const __half* __restrict__ A, const __half* __restrict__ B,
              float* __restrict__ C, const float* __restrict__ bias)
{
    extern __shared__ __align__(1024) __half smem[];
    __half* sA = smem;
    __half* sB = smem + STAGES * 128 * BK;

    const int tid = threadIdx.x, wid = tid >> 5, lane = tid & 31;
    const int m0 = blockIdx.y * 128, n0 = blockIdx.x * 128;
    const int wm = wid & 1, wn = wid >> 1;

    float acc[4][8][4];
    #pragma unroll
    for (int i = 0; i < 4; i++)
        #pragma unroll
        for (int j = 0; j < 8; j++)
            #pragma unroll
            for (int t = 0; t < 4; t++) acc[i][j][t] = 0.f;

    const uint32_t saA = smem_u32(sA), saB = smem_u32(sB);

    auto fill = [&](int kt) {
        const int st = kt % STAGES;
        const uint32_t da = saA + st * STAGE_BYTES;
        const uint32_t db = saB + st * STAGE_BYTES;
        const int k0 = kt * BK;
        #pragma unroll
        for (int i = 0; i < 8; i++) {
            int idx = tid + i * 128;
            int r = idx >> 3, c = idx & 7;
            uint32_t sw = sw128((uint32_t)(r * 128 + c * 16));
            cp_async16(da + sw, A + (size_t)(m0 + r) * K2 + k0 + c * 8);
        }
        #pragma unroll
        for (int i = 0; i < 8; i++) {
            int idx = tid + i * 128;
            int r = idx >> 3, c = idx & 7;
            uint32_t sw = sw128((uint32_t)(r * 128 + c * 16));
            cp_async16(db + sw, B + (size_t)(n0 + r) * K2 + k0 + c * 8);
        }
        asm volatile("cp.async.commit_group;\n" ::: "memory");
    };

    const uint32_t a_row  = (uint32_t)(wm * 64 + (lane & 15));
    const uint32_t a_kh   = (uint32_t)((lane >> 4) * 16);
    const uint32_t b_row  = (uint32_t)(wn * 64 + ((lane >> 4) << 3) + (lane & 7));
    const uint32_t b_kh   = (uint32_t)(((lane >> 3) & 1) * 16);

    const int KT = K2 / BK;    // 9

    #pragma unroll
    for (int kt = 0; kt < STAGES - 1; kt++) fill(kt);

    for (int kt = 0; kt < KT; kt++) {
        asm volatile("cp.async.wait_group %0;\n" :: "n"(STAGES - 2) : "memory");
        __syncthreads();

        if (kt + STAGES - 1 < KT) fill(kt + STAGES - 1);
        else asm volatile("cp.async.commit_group;\n" ::: "memory");

        const int st = kt % STAGES;
        const uint32_t da = saA + st * STAGE_BYTES;
        const uint32_t db = saB + st * STAGE_BYTES;
        #pragma unroll
        for (int k16 = 0; k16 < BK / 16; k16++) {
            uint32_t af[4][4], bf[4][4];
            #pragma unroll
            for (int mt = 0; mt < 4; mt++) {
                uint32_t off = (a_row + mt * 16) * 128 + a_kh + k16 * 32;
                ldm_x4(af[mt], da + sw128(off));
            }
            #pragma unroll
            for (int np = 0; np < 4; np++) {
                uint32_t off = (b_row + np * 16) * 128 + b_kh + k16 * 32;
                ldm_x4(bf[np], db + sw128(off));
            }
            #pragma unroll
            for (int mt = 0; mt < 4; mt++)
                #pragma unroll
                for (int nt = 0; nt < 8; nt++)
                    mma16816(acc[mt][nt], af[mt], &bf[nt >> 1][(nt & 1) * 2]);
        }
    }

    const int er = lane >> 2, ec = (lane & 3) * 2;
    #pragma unroll
    for (int mt = 0; mt < 4; mt++) {
        #pragma unroll
        for (int nt = 0; nt < 8; nt++) {
            int row = m0 + wm * 64 + mt * 16 + er;
            int col = n0 + wn * 64 + nt * 8 + ec;
            float b0 = bias[col], b1 = bias[col + 1];
            float2 v0 = { acc[mt][nt][0] + b0, acc[mt][nt][1] + b1 };
            float2 v1 = { acc[mt][nt][2] + b0, acc[mt][nt][3] + b1 };
            *(float2*)(C + (size_t)row * 512 + col)       = v0;
            *(float2*)(C + (size_t)(row + 8) * 512 + col) = v1;
        }
    }
}

// ---------------- per-row attention (block = row, warp = head) -----------------
__global__ __launch_bounds__(256)
void attn_kernel(const int* __restrict__ col_index, const int* __restrict__ to_col,
                 const float* __restrict__ att_bias, const float* __restrict__ dist,
                 const float* __restrict__ pos, const float* __restrict__ col_pos)
{
    __shared__ int   s_cn[DEG];
    __shared__ float s_cp[DEG][3];
    __shared__ float s_rel[DEG][3];
    __shared__ float s_de[DEG];
    __shared__ float s_att[H_HEADS][DEG];

    int row = blockIdx.x;
    int tid = threadIdx.x;

    if (tid < DEG) {
        int is64 = g_idx64;
        int e  = row * DEG + tid;
        int c  = ldidx(col_index, e, is64);
        int cn = ldidx(to_col,   c, is64);
        s_cn[tid] = cn;
        float px = pos[row*3+0], py = pos[row*3+1], pz = pos[row*3+2];
        float cx = col_pos[c*3+0], cy = col_pos[c*3+1], cz = col_pos[c*3+2];
        s_cp[tid][0]  = cx;      s_cp[tid][1]  = cy;      s_cp[tid][2]  = cz;
        s_rel[tid][0] = cx - px; s_rel[tid][1] = cy - py; s_rel[tid][2] = cz - pz;
        float d0 = dist[e];
        s_de[tid] = (d0 == 0.f) ? INFINITY : d0;
    }
    __syncthreads();

    int h = tid >> 5, lane = tid & 31;
    __half* a2row = g_A2 + (size_t)row * K2;

    const float4* q4 = (const float4*)(g_Q + (size_t)row * 512 + h * DKV);
    float4 qf = q4[lane & 15];
    const float* qvp = g_QV + (size_t)row * 128 + h * 3;
    float a0 = qvp[0], a1 = qvp[1], a2 = qvp[2];

    // logits: half-warp per edge, 2 edges per iteration, fp16 k gathers
    float mylogit = -INFINITY;
    #pragma unroll
    for (int i = 0; i < 8; i++) {
        int j = 2 * i + (lane >> 4);
        const uint2* kp = (const uint2*)(g_K + (size_t)s_cn[j] * 512 + h * DKV);
        uint2 kraw = kp[lane & 15];
        float2 f01 = __half22float2(*(__half2*)&kraw.x);
        float2 f23 = __half22float2(*(__half2*)&kraw.y);
        float p = qf.x*f01.x + qf.y*f01.y + qf.z*f23.x + qf.w*f23.y;
        #pragma unroll
        for (int o = 8; o; o >>= 1) p += __shfl_xor_sync(0xffffffffu, p, o);
        float tmp = __shfl_sync(0xffffffffu, p, (lane & 1) << 4);
        if ((lane >> 1) == i) mylogit = tmp;
    }
    if (lane < DEG) {
        float ang = a0*s_rel[lane][0] + a1*s_rel[lane][1] + a2*s_rel[lane][2];
        mylogit += att_bias[(size_t)h * E_EDGES + row * DEG + lane] + ang / s_de[lane];
    }

    // softmax over lanes 0..15
    float m = mylogit;
    #pragma unroll
    for (int o = 16; o; o >>= 1) m = fmaxf(m, __shfl_xor_sync(0xffffffffu, m, o));
    float pe = (lane < DEG) ? expf(mylogit - m) : 0.f;
    float ss = pe;
    #pragma unroll
    for (int o = 16; o; o >>= 1) ss += __shfl_xor_sync(0xffffffffu, ss, o);
    float att  = pe / ss;
    float natt = (lane < DEG) ? att / s_de[lane] : 0.f;
    if (lane < DEG) s_att[h][lane] = att;

    float d0v = (lane < DEG) ? natt * s_cp[lane][0] : 0.f;
    float d1v = (lane < DEG) ? natt * s_cp[lane][1] : 0.f;
    float d2v = (lane < DEG) ? natt * s_cp[lane][2] : 0.f;
    float avg = natt;
    #pragma unroll
    for (int o = 16; o; o >>= 1) {
        d0v += __shfl_xor_sync(0xffffffffu, d0v, o);
        d1v += __shfl_xor_sync(0xffffffffu, d1v, o);
        d2v += __shfl_xor_sync(0xffffffffu, d2v, o);
        avg += __shfl_xor_sync(0xffffffffu, avg, o);
    }
    int kb = h * (DKV + 4);
    if (lane == 0) {
        float px = pos[row*3+0], py = pos[row*3+1], pz = pos[row*3+2];
        float dx = d0v - avg*px, dy = d1v - avg*py, dz = d2v - avg*pz;
        float nrm = sqrtf(dx*dx + dy*dy + dz*dz);
        float inv = 1.f / fmaxf(nrm, 1e-12f);
        *(__half2*)(a2row + kb + DKV + 0) = __floats2half2_rn(dx*inv, dy*inv);
        *(__half2*)(a2row + kb + DKV + 2) = __floats2half2_rn(dz*inv, avg);
    }
    __syncwarp();

    // y = att @ V (fp16 gather), float2 per lane (dims 2*lane, 2*lane+1)
    float2 acc2 = {0.f, 0.f};
    #pragma unroll
    for (int j = 0; j < DEG; j++) {
        const __half2* vp2 = (const __half2*)(g_V + (size_t)s_cn[j] * 512 + h * DKV);
        float2 v = __half22float2(vp2[lane]);
        float a = s_att[h][j];
        acc2.x += a * v.x;
        acc2.y += a * v.y;
    }
    *(__half2*)(a2row + kb + 2 * lane) = __floats2half2_rn(acc2.x, acc2.y);
}

// ---------------- launch --------------------------------------------------------
extern "C" void kernel_launch(void* const* d_in, const int* in_sizes, int n_in,
                              void* d_out, int out_size)
{
    const float* x         = (const float*)d_in[0];
    const int*   col_index = (const int*)  d_in[2];
    const int*   to_col    = (const int*)  d_in[3];
    const float* att_bias  = (const float*)d_in[4];
    const float* dist      = (const float*)d_in[5];
    const float* pos       = (const float*)d_in[6];
    const float* col_pos   = (const float*)d_in[7];
    const float* Wq        = (const float*)d_in[8];
    const float* Wqv       = (const float*)d_in[9];
    const float* Wk        = (const float*)d_in[10];
    const float* Wv        = (const float*)d_in[11];
    const float* Wout      = (const float*)d_in[12];
    const float* bout      = (const float*)d_in[13];
    float*       out       = (float*)d_out;

    void *pA1, *pB1, *pA2, *pB2;
    cudaGetSymbolAddress(&pA1, g_A1);
    cudaGetSymbolAddress(&pB1, g_B1);
    cudaGetSymbolAddress(&pA2, g_A2);
    cudaGetSymbolAddress(&pB2, g_B2);

    const int SMEM = STAGES * 2 * STAGE_BYTES;     // 98304
    cudaFuncSetAttribute(gemm_proj, cudaFuncAttributeMaxDynamicSharedMemorySize, SMEM);
    cudaFuncSetAttribute(gemm_out,  cudaFuncAttributeMaxDynamicSharedMemorySize, SMEM);

    conv_all<<<CONV_BLOCKS, 256>>>(x, Wq, Wk, Wv, Wqv, Wout, col_index);

    dim3 g1(13, N_NODES / 128);                // 4 q + 4 k + 4 v + 1 qv tiles
    gemm_proj<<<g1, 128, SMEM>>>((const __half*)pA1, (const __half*)pB1);

    attn_kernel<<<N_NODES, 256>>>(col_index, to_col, att_bias, dist, pos, col_pos);

    dim3 g2(512 / 128, N_NODES / 128);         // 4 x 64
    gemm_out<<<g2, 128, SMEM>>>((const __half*)pA2, (const __half*)pB2, out, bout);
}